// round 2
// baseline (speedup 1.0000x reference)
#include <cuda_runtime.h>
#include <math.h>

#define BN   64
#define N1P  8192
#define NV   778
#define VP   780      // padded to multiple of 4
#define NFC  1538
#define NP   204
#define PP   208      // padded prior count

__device__ double g_acc[8];          // 0:cmap_sum 1:n_points 2:consist 3:gt_cnt 4:penetr 5:chamfer
__device__ float  g_vn[BN * 3 * NV]; // per-batch SoA vertex normals

__constant__ int c_prior[NP] = {
697,698,699,700,712,713,714,715,737,738,739,740,741,743,744,745,746,748,749,750,
753,754,755,756,757,758,759,760,761,762,763,764,765,766,767,768,
46,47,48,49,164,165,166,167,194,195,223,237,238,280,281,298,301,317,320,323,
324,325,326,327,328,329,330,331,332,333,340,341,342,343,344,345,346,347,348,349,
350,351,352,353,354,355,
356,357,358,359,375,376,386,387,396,397,402,403,413,429,433,434,435,436,437,438,
439,440,441,442,443,444,452,453,454,455,456,459,460,461,462,463,464,465,466,467,
468,469,470,471,484,485,486,496,497,506,507,513,514,524,545,546,547,548,549,550,
551,552,553,555,563,564,565,566,567,570,572,573,574,575,576,577,578,
580,581,582,583,600,601,602,614,615,624,625,630,631,641,663,664,665,666,667,668,
670,672,680,681,682,683,684,686,687,688,689,690,691,692,693,694,695,
73,96,98,99,772,774,775,777};

__global__ void k_zero() {
    if (threadIdx.x < 8) g_acc[threadIdx.x] = 0.0;
}

// ---------------- vertex normals: one block per batch ----------------
__global__ void k_normals(const float* __restrict__ recon, const int* __restrict__ faces) {
    __shared__ float sx[NV], sy[NV], sz[NV];
    __shared__ float nx[NV], ny[NV], nz[NV];
    const int b = blockIdx.x, tid = threadIdx.x;
    const float* rb = recon + (size_t)b * NV * 3;
    for (int v = tid; v < NV; v += blockDim.x) {
        sx[v] = rb[3*v+0]; sy[v] = rb[3*v+1]; sz[v] = rb[3*v+2];
        nx[v] = 0.f; ny[v] = 0.f; nz[v] = 0.f;
    }
    __syncthreads();
    for (int f = tid; f < NFC; f += blockDim.x) {
        int i0 = faces[3*f+0], i1 = faces[3*f+1], i2 = faces[3*f+2];
        float e1x = sx[i1]-sx[i0], e1y = sy[i1]-sy[i0], e1z = sz[i1]-sz[i0];
        float e2x = sx[i2]-sx[i0], e2y = sy[i2]-sy[i0], e2z = sz[i2]-sz[i0];
        float fx = e1y*e2z - e1z*e2y;
        float fy = e1z*e2x - e1x*e2z;
        float fz = e1x*e2y - e1y*e2x;
        atomicAdd(&nx[i0], fx); atomicAdd(&ny[i0], fy); atomicAdd(&nz[i0], fz);
        atomicAdd(&nx[i1], fx); atomicAdd(&ny[i1], fy); atomicAdd(&nz[i1], fz);
        atomicAdd(&nx[i2], fx); atomicAdd(&ny[i2], fy); atomicAdd(&nz[i2], fz);
    }
    __syncthreads();
    float* vb = g_vn + (size_t)b * 3 * NV;
    for (int v = tid; v < NV; v += blockDim.x) {
        float x = nx[v], y = ny[v], z = nz[v];
        float inv = 1.f / (sqrtf(x*x + y*y + z*z) + 1e-12f);
        vb[v] = x*inv; vb[NV+v] = y*inv; vb[2*NV+v] = z*inv;
    }
}

// ---------------- recon<->gt bidirectional chamfer ----------------
__global__ void k_chamfer(const float* __restrict__ recon, const float* __restrict__ gt) {
    __shared__ __align__(16) float rx[VP], ry[VP], rz[VP], gx[VP], gy[VP], gz[VP];
    __shared__ float s_red[8];
    const int b = blockIdx.y, tid = threadIdx.x;
    const float* rb = recon + (size_t)b * NV * 3;
    const float* gb = gt    + (size_t)b * NV * 3;
    for (int v = tid; v < VP; v += 256) {
        if (v < NV) {
            rx[v] = rb[3*v+0]; ry[v] = rb[3*v+1]; rz[v] = rb[3*v+2];
            gx[v] = gb[3*v+0]; gy[v] = gb[3*v+1]; gz[v] = gb[3*v+2];
        } else {
            rx[v] = 1e18f; ry[v] = 1e18f; rz[v] = 1e18f;
            gx[v] = 1e18f; gy[v] = 1e18f; gz[v] = 1e18f;
        }
    }
    __syncthreads();
    const int r = blockIdx.x * 256 + tid;
    float sum = 0.f;
    if (r < NV) {
        float ax = rx[r], ay = ry[r], az = rz[r];
        float dmin = 3e38f;
        #pragma unroll 4
        for (int j = 0; j < VP; j++) {
            float dx = ax - gx[j], dy = ay - gy[j], dz = az - gz[j];
            float d = fmaf(dz, dz, fmaf(dy, dy, dx*dx));
            dmin = fminf(dmin, d);
        }
        sum += fmaxf(dmin, 0.f);
        ax = gx[r]; ay = gy[r]; az = gz[r];
        dmin = 3e38f;
        #pragma unroll 4
        for (int j = 0; j < VP; j++) {
            float dx = ax - rx[j], dy = ay - ry[j], dz = az - rz[j];
            float d = fmaf(dz, dz, fmaf(dy, dy, dx*dx));
            dmin = fminf(dmin, d);
        }
        sum += fmaxf(dmin, 0.f);
    }
    for (int off = 16; off; off >>= 1) sum += __shfl_down_sync(0xFFFFFFFFu, sum, off);
    if ((tid & 31) == 0) s_red[tid >> 5] = sum;
    __syncthreads();
    if (tid == 0) {
        float t = 0.f;
        for (int w = 0; w < 8; w++) t += s_red[w];
        atomicAdd(&g_acc[5], (double)t);
    }
}

// ---------------- main kernel: obj vs {gt, recon, prior} ----------------
__global__ __launch_bounds__(128) void k_main(const float* __restrict__ obj,
                                              const float* __restrict__ recon,
                                              const float* __restrict__ gt) {
    __shared__ __align__(16) float rmx[VP], rmy[VP], rmz[VP], rcc[VP];
    __shared__ __align__(16) float tmx[VP], tmy[VP], tmz[VP], tcc[VP];
    __shared__ __align__(16) float pmx[PP], pmy[PP], pmz[PP], pcc[PP];
    __shared__ float s_red[20];

    const int b = blockIdx.y;
    const int tid = threadIdx.x;
    const float* rb = recon + (size_t)b * NV * 3;
    const float* gb = gt    + (size_t)b * NV * 3;
    for (int v = tid; v < VP; v += 128) {
        if (v < NV) {
            float x = rb[3*v+0], y = rb[3*v+1], z = rb[3*v+2];
            rmx[v] = -2.f*x; rmy[v] = -2.f*y; rmz[v] = -2.f*z;
            rcc[v] = fmaf(z, z, fmaf(y, y, x*x));
            x = gb[3*v+0]; y = gb[3*v+1]; z = gb[3*v+2];
            tmx[v] = -2.f*x; tmy[v] = -2.f*y; tmz[v] = -2.f*z;
            tcc[v] = fmaf(z, z, fmaf(y, y, x*x));
        } else {
            rmx[v]=0.f; rmy[v]=0.f; rmz[v]=0.f; rcc[v]=3e37f;
            tmx[v]=0.f; tmy[v]=0.f; tmz[v]=0.f; tcc[v]=3e37f;
        }
    }
    __syncthreads();
    for (int i = tid; i < PP; i += 128) {
        if (i < NP) {
            int j = c_prior[i];
            pmx[i]=rmx[j]; pmy[i]=rmy[j]; pmz[i]=rmz[j]; pcc[i]=rcc[j];
        } else { pmx[i]=0.f; pmy[i]=0.f; pmz[i]=0.f; pcc[i]=3e37f; }
    }
    __syncthreads();

    float ax0, ay0, az0, a20, ax1, ay1, az1, a21;
    {
        const int p0 = blockIdx.x * 256 + tid;
        const float* o0 = obj + ((size_t)b * N1P + p0) * 3;
        ax0 = o0[0]; ay0 = o0[1]; az0 = o0[2];
        const float* o1 = o0 + 128 * 3;
        ax1 = o1[0]; ay1 = o1[1]; az1 = o1[2];
        a20 = fmaf(az0, az0, fmaf(ay0, ay0, ax0*ax0));
        a21 = fmaf(az1, az1, fmaf(ay1, ay1, ax1*ax1));
    }

    float dg0 = 3e38f, dg1 = 3e38f, dp0 = 3e38f, dp1 = 3e38f;
    int   k0  = 0x7FFFFFFF, k1 = 0x7FFFFFFF;

#define GSTEP(X,Y,Z,C) { \
    float d0 = fmaf(az0,(Z),fmaf(ay0,(Y),fmaf(ax0,(X),a20+(C)))); \
    float d1 = fmaf(az1,(Z),fmaf(ay1,(Y),fmaf(ax1,(X),a21+(C)))); \
    dg0 = fminf(dg0, d0); dg1 = fminf(dg1, d1); }
    #pragma unroll 2
    for (int t = 0; t < VP; t += 4) {
        float4 vx = *(const float4*)(tmx + t);
        float4 vy = *(const float4*)(tmy + t);
        float4 vz = *(const float4*)(tmz + t);
        float4 vc = *(const float4*)(tcc + t);
        GSTEP(vx.x, vy.x, vz.x, vc.x)
        GSTEP(vx.y, vy.y, vz.y, vc.y)
        GSTEP(vx.z, vy.z, vz.z, vc.z)
        GSTEP(vx.w, vy.w, vz.w, vc.w)
    }

#define RSTEP(X,Y,Z,C,J) { \
    float d0 = fmaf(az0,(Z),fmaf(ay0,(Y),fmaf(ax0,(X),a20+(C)))); \
    float d1 = fmaf(az1,(Z),fmaf(ay1,(Y),fmaf(ax1,(X),a21+(C)))); \
    int q0 = (__float_as_int(d0) & 0xFFFFFC00) | (J); \
    int q1 = (__float_as_int(d1) & 0xFFFFFC00) | (J); \
    k0 = min(k0, q0); k1 = min(k1, q1); }
    #pragma unroll 2
    for (int t = 0; t < VP; t += 4) {
        float4 vx = *(const float4*)(rmx + t);
        float4 vy = *(const float4*)(rmy + t);
        float4 vz = *(const float4*)(rmz + t);
        float4 vc = *(const float4*)(rcc + t);
        RSTEP(vx.x, vy.x, vz.x, vc.x, t)
        RSTEP(vx.y, vy.y, vz.y, vc.y, t + 1)
        RSTEP(vx.z, vy.z, vz.z, vc.z, t + 2)
        RSTEP(vx.w, vy.w, vz.w, vc.w, t + 3)
    }

#define PSTEP(X,Y,Z,C) { \
    float d0 = fmaf(az0,(Z),fmaf(ay0,(Y),fmaf(ax0,(X),a20+(C)))); \
    float d1 = fmaf(az1,(Z),fmaf(ay1,(Y),fmaf(ax1,(X),a21+(C)))); \
    dp0 = fminf(dp0, d0); dp1 = fminf(dp1, d1); }
    #pragma unroll 2
    for (int t = 0; t < PP; t += 4) {
        float4 vx = *(const float4*)(pmx + t);
        float4 vy = *(const float4*)(pmy + t);
        float4 vz = *(const float4*)(pmz + t);
        float4 vc = *(const float4*)(pcc + t);
        PSTEP(vx.x, vy.x, vz.x, vc.x)
        PSTEP(vx.y, vy.y, vz.y, vc.y)
        PSTEP(vx.z, vy.z, vz.z, vc.z)
        PSTEP(vx.w, vy.w, vz.w, vc.w)
    }

    float cm = 0.f, pen = 0.f, npn = 0.f, cons = 0.f, gtc = 0.f;
    const float* vb = g_vn + (size_t)b * 3 * NV;
#define EPILOGUE(K, DG, DP, AX, AY, AZ) { \
    float drec = fmaxf(__int_as_float((K) & 0xFFFFFC00), 0.f); \
    int idx = (K) & 1023; \
    float dgt = fmaxf((DG), 0.f); \
    float dpr = fmaxf((DP), 0.f); \
    if (drec < 1e-4f) { cm += dpr; npn += 1.f; } \
    bool rc = sqrtf(drec) < 0.005f; \
    bool gc = sqrtf(dgt)  < 0.005f; \
    if (gc) { gtc += 1.f; if (rc) cons += 1.f; } \
    float nvx = -0.5f*rmx[idx], nvy = -0.5f*rmy[idx], nvz = -0.5f*rmz[idx]; \
    float dot = (nvx-(AX))*vb[idx] + (nvy-(AY))*vb[NV+idx] + (nvz-(AZ))*vb[2*NV+idx]; \
    if (dot > 0.f) pen += drec; }
    EPILOGUE(k0, dg0, dp0, ax0, ay0, az0)
    EPILOGUE(k1, dg1, dp1, ax1, ay1, az1)

    for (int off = 16; off; off >>= 1) {
        cm   += __shfl_down_sync(0xFFFFFFFFu, cm,   off);
        pen  += __shfl_down_sync(0xFFFFFFFFu, pen,  off);
        npn  += __shfl_down_sync(0xFFFFFFFFu, npn,  off);
        cons += __shfl_down_sync(0xFFFFFFFFu, cons, off);
        gtc  += __shfl_down_sync(0xFFFFFFFFu, gtc,  off);
    }
    const int wid = tid >> 5, lane = tid & 31;
    if (lane == 0) {
        s_red[wid]      = cm;   s_red[4 + wid]  = pen;
        s_red[8 + wid]  = npn;  s_red[12 + wid] = cons;
        s_red[16 + wid] = gtc;
    }
    __syncthreads();
    if (tid == 0) {
        float c = 0, p = 0, n = 0, co = 0, g = 0;
        for (int w = 0; w < 4; w++) {
            c += s_red[w]; p += s_red[4+w]; n += s_red[8+w];
            co += s_red[12+w]; g += s_red[16+w];
        }
        atomicAdd(&g_acc[0], (double)c);
        atomicAdd(&g_acc[4], (double)p);
        atomicAdd(&g_acc[1], (double)n);
        atomicAdd(&g_acc[2], (double)co);
        atomicAdd(&g_acc[3], (double)g);
    }
}

// ---------------- final combine ----------------
__global__ void k_final(const float* __restrict__ mean, const float* __restrict__ logv,
                        const float* __restrict__ rp, const float* __restrict__ xp,
                        float* __restrict__ out) {
    __shared__ float s1[8], s2[8];
    const int tid = threadIdx.x;
    float sp = 0.f, sk = 0.f;
    for (int i = tid; i < BN * 61; i += 256) { float d = rp[i] - xp[i]; sp += d*d; }
    for (int i = tid; i < BN * 64; i += 256) {
        float m = mean[i], lv = logv[i];
        sk += 1.f + lv - m*m - expf(lv);
    }
    for (int off = 16; off; off >>= 1) {
        sp += __shfl_down_sync(0xFFFFFFFFu, sp, off);
        sk += __shfl_down_sync(0xFFFFFFFFu, sk, off);
    }
    if ((tid & 31) == 0) { s1[tid >> 5] = sp; s2[tid >> 5] = sk; }
    __syncthreads();
    if (tid == 0) {
        float spt = 0.f, skt = 0.f;
        for (int w = 0; w < 8; w++) { spt += s1[w]; skt += s2[w]; }
        double param_loss  = (double)spt / 64.0;
        double KLD         = -0.5 * (double)skt / 64.0 * 10.0;
        double recon_loss  = g_acc[5] / 64.0;
        double cmap_loss   = 3000.0 * g_acc[0] / (64.0 * g_acc[1]);
        double consistency = -5.0 * g_acc[2] / (g_acc[3] + 0.0001);
        double penetr      = 100.0 * g_acc[4] / 64.0;
        double loss = (recon_loss + KLD) + 0.1 * param_loss
                    + 1000.0 * cmap_loss + 10.0 * consistency + 10.0 * penetr;
        out[0] = (float)loss;
    }
}

extern "C" void kernel_launch(void* const* d_in, const int* in_sizes, int n_in,
                              void* d_out, int out_size) {
    const float* obj   = (const float*)d_in[0];
    const float* recon = (const float*)d_in[1];
    const float* gt    = (const float*)d_in[2];
    const float* mean  = (const float*)d_in[3];
    const float* logv  = (const float*)d_in[4];
    const float* rp    = (const float*)d_in[5];
    const float* xp    = (const float*)d_in[6];
    const int*   faces = (const int*)d_in[7];
    float* out = (float*)d_out;

    k_zero<<<1, 32>>>();
    k_normals<<<BN, 256>>>(recon, faces);
    k_chamfer<<<dim3((NV + 255) / 256, BN), 256>>>(recon, gt);
    k_main<<<dim3(N1P / 256, BN), 128>>>(obj, recon, gt);
    k_final<<<1, 256>>>(mean, logv, rp, xp, out);
}

// round 4
// speedup vs baseline: 1.1701x; 1.1701x over previous
#include <cuda_runtime.h>
#include <math.h>

#define BN   64
#define N1P  8192
#define NV   778
#define VP   780      // padded to multiple of 4
#define NFC  1538
#define NP   204
#define PP   208      // padded prior count

#define PTS        4                       // obj points per thread in k_main
#define MAIN_TPB   128
#define MAIN_GX    (N1P / (MAIN_TPB * PTS))   // 16
#define NBLK_MAIN  (MAIN_GX * BN)             // 1024
#define NBLK_CHAM  (8 * BN)                   // 512

__device__ float g_vn[BN * 3 * NV];        // per-batch SoA vertex normals
__device__ float g_part_main[NBLK_MAIN * 5];
__device__ float g_part_cham[NBLK_CHAM];

__constant__ int c_prior[NP] = {
697,698,699,700,712,713,714,715,737,738,739,740,741,743,744,745,746,748,749,750,
753,754,755,756,757,758,759,760,761,762,763,764,765,766,767,768,
46,47,48,49,164,165,166,167,194,195,223,237,238,280,281,298,301,317,320,323,
324,325,326,327,328,329,330,331,332,333,340,341,342,343,344,345,346,347,348,349,
350,351,352,353,354,355,
356,357,358,359,375,376,386,387,396,397,402,403,413,429,433,434,435,436,437,438,
439,440,441,442,443,444,452,453,454,455,456,459,460,461,462,463,464,465,466,467,
468,469,470,471,484,485,486,496,497,506,507,513,514,524,545,546,547,548,549,550,
551,552,553,555,563,564,565,566,567,570,572,573,574,575,576,577,578,
580,581,582,583,600,601,602,614,615,624,625,630,631,641,663,664,665,666,667,668,
670,672,680,681,682,683,684,686,687,688,689,690,691,692,693,694,695,
73,96,98,99,772,774,775,777};

// ---- packed f32x2 helpers (sm_103a) ----
typedef unsigned long long u64;

__device__ __forceinline__ u64 ffma2(u64 a, u64 b, u64 c) {
    u64 d;
    asm("fma.rn.f32x2 %0, %1, %2, %3;" : "=l"(d) : "l"(a), "l"(b), "l"(c));
    return d;
}
__device__ __forceinline__ u64 fadd2(u64 a, u64 b) {
    u64 d;
    asm("add.rn.f32x2 %0, %1, %2;" : "=l"(d) : "l"(a), "l"(b));
    return d;
}
__device__ __forceinline__ u64 bcast2(float x) {
    u64 r;
    asm("mov.b64 %0, {%1, %2};" : "=l"(r) : "f"(x), "f"(x));
    return r;
}
__device__ __forceinline__ void unpack2f(u64 v, float& lo, float& hi) {
    asm("mov.b64 {%0, %1}, %2;" : "=f"(lo), "=f"(hi) : "l"(v));
}
__device__ __forceinline__ void unpack2i(u64 v, int& lo, int& hi) {
    asm("mov.b64 {%0, %1}, %2;" : "=r"(lo), "=r"(hi) : "l"(v));
}

// ================= fused: vertex normals + recon<->gt chamfer =================
// blocks [0,64): normals (one per batch); blocks [64,576): chamfer
__global__ __launch_bounds__(256) void k_pre(const float* __restrict__ recon,
                                             const float* __restrict__ gt,
                                             const int* __restrict__ faces) {
    __shared__ __align__(16) float sm[6 * NV];   // 18.7KB, reused by both paths
    __shared__ float red[8];
    const int tid = threadIdx.x;

    if (blockIdx.x < BN) {
        // ---------- vertex normals ----------
        const int b = blockIdx.x;
        float* sx = sm;         float* sy = sm + NV;     float* sz = sm + 2 * NV;
        float* nx = sm + 3 * NV; float* ny = sm + 4 * NV; float* nz = sm + 5 * NV;
        const float* rb = recon + (size_t)b * NV * 3;
        for (int v = tid; v < NV; v += 256) {
            sx[v] = rb[3*v+0]; sy[v] = rb[3*v+1]; sz[v] = rb[3*v+2];
            nx[v] = 0.f; ny[v] = 0.f; nz[v] = 0.f;
        }
        __syncthreads();
        for (int f = tid; f < NFC; f += 256) {
            int i0 = faces[3*f+0], i1 = faces[3*f+1], i2 = faces[3*f+2];
            float e1x = sx[i1]-sx[i0], e1y = sy[i1]-sy[i0], e1z = sz[i1]-sz[i0];
            float e2x = sx[i2]-sx[i0], e2y = sy[i2]-sy[i0], e2z = sz[i2]-sz[i0];
            float fx = e1y*e2z - e1z*e2y;
            float fy = e1z*e2x - e1x*e2z;
            float fz = e1x*e2y - e1y*e2x;
            atomicAdd(&nx[i0], fx); atomicAdd(&ny[i0], fy); atomicAdd(&nz[i0], fz);
            atomicAdd(&nx[i1], fx); atomicAdd(&ny[i1], fy); atomicAdd(&nz[i1], fz);
            atomicAdd(&nx[i2], fx); atomicAdd(&ny[i2], fy); atomicAdd(&nz[i2], fz);
        }
        __syncthreads();
        float* vb = g_vn + (size_t)b * 3 * NV;
        for (int v = tid; v < NV; v += 256) {
            float x = nx[v], y = ny[v], z = nz[v];
            float inv = 1.f / (sqrtf(x*x + y*y + z*z) + 1e-12f);
            vb[v] = x*inv; vb[NV+v] = y*inv; vb[2*NV+v] = z*inv;
        }
        return;
    }

    // ---------- chamfer: one direction-rowblock per block ----------
    const int cb  = blockIdx.x - BN;        // 0..511
    const int b   = cb >> 3;
    const int sub = cb & 7;                 // 0..3: recon->gt rows; 4..7: gt->recon
    const float* src; const float* tgt;
    int rowblk;
    if (sub < 4) { src = recon + (size_t)b * NV * 3; tgt = gt    + (size_t)b * NV * 3; rowblk = sub; }
    else         { src = gt    + (size_t)b * NV * 3; tgt = recon + (size_t)b * NV * 3; rowblk = sub - 4; }

    float* tx2 = sm;            float* ty2 = sm + VP;
    float* tz2 = sm + 2 * VP;   float* tc  = sm + 3 * VP;
    for (int v = tid; v < VP; v += 256) {
        if (v < NV) {
            float x = tgt[3*v+0], y = tgt[3*v+1], z = tgt[3*v+2];
            tx2[v] = -2.f*x; ty2[v] = -2.f*y; tz2[v] = -2.f*z;
            tc[v]  = fmaf(z, z, fmaf(y, y, x*x));
        } else { tx2[v] = 0.f; ty2[v] = 0.f; tz2[v] = 0.f; tc[v] = 3e37f; }
    }
    __syncthreads();

    const int row = rowblk * 256 + tid;
    float partial = 0.f;
    if (row < NV) {
        float ax = src[3*row+0], ay = src[3*row+1], az = src[3*row+2];
        float a2 = fmaf(az, az, fmaf(ay, ay, ax*ax));
        u64 AX = bcast2(ax), AY = bcast2(ay), AZ = bcast2(az);
        float m0 = 3e38f, m1 = 3e38f;
        #pragma unroll 1
        for (int t = 0; t < VP; t += 4) {
            ulonglong2 X = *(const ulonglong2*)(tx2 + t);
            ulonglong2 Y = *(const ulonglong2*)(ty2 + t);
            ulonglong2 Z = *(const ulonglong2*)(tz2 + t);
            ulonglong2 C = *(const ulonglong2*)(tc  + t);
            u64 d2 = ffma2(AZ, Z.x, ffma2(AY, Y.x, ffma2(AX, X.x, C.x)));
            float lo, hi; unpack2f(d2, lo, hi);
            m0 = fminf(m0, lo); m1 = fminf(m1, hi);
            d2 = ffma2(AZ, Z.y, ffma2(AY, Y.y, ffma2(AX, X.y, C.y)));
            unpack2f(d2, lo, hi);
            m0 = fminf(m0, lo); m1 = fminf(m1, hi);
        }
        partial = fmaxf(fminf(m0, m1) + a2, 0.f);
    }
    for (int off = 16; off; off >>= 1) partial += __shfl_down_sync(0xFFFFFFFFu, partial, off);
    if ((tid & 31) == 0) red[tid >> 5] = partial;
    __syncthreads();
    if (tid == 0) {
        float t = 0.f;
        for (int w = 0; w < 8; w++) t += red[w];
        g_part_cham[cb] = t;
    }
}

// ================= main kernel: obj vs {gt, recon, prior} =================
__global__ __launch_bounds__(MAIN_TPB) void k_main(const float* __restrict__ obj,
                                                   const float* __restrict__ recon,
                                                   const float* __restrict__ gt) {
    __shared__ __align__(16) float rmx[VP], rmy[VP], rmz[VP], rcc[VP];
    __shared__ __align__(16) float tmx[VP], tmy[VP], tmz[VP], tcc[VP];
    __shared__ __align__(16) float pmx[PP], pmy[PP], pmz[PP], pcc[PP];
    __shared__ float s_red[20];

    const int b   = blockIdx.y;
    const int tid = threadIdx.x;
    const float* rb = recon + (size_t)b * NV * 3;
    const float* gb = gt    + (size_t)b * NV * 3;
    for (int v = tid; v < VP; v += MAIN_TPB) {
        if (v < NV) {
            float x = rb[3*v+0], y = rb[3*v+1], z = rb[3*v+2];
            rmx[v] = -2.f*x; rmy[v] = -2.f*y; rmz[v] = -2.f*z;
            rcc[v] = fmaf(z, z, fmaf(y, y, x*x));
            x = gb[3*v+0]; y = gb[3*v+1]; z = gb[3*v+2];
            tmx[v] = -2.f*x; tmy[v] = -2.f*y; tmz[v] = -2.f*z;
            tcc[v] = fmaf(z, z, fmaf(y, y, x*x));
        } else {
            rmx[v]=0.f; rmy[v]=0.f; rmz[v]=0.f; rcc[v]=3e37f;
            tmx[v]=0.f; tmy[v]=0.f; tmz[v]=0.f; tcc[v]=3e37f;
        }
    }
    __syncthreads();
    for (int i = tid; i < PP; i += MAIN_TPB) {
        if (i < NP) {
            int j = c_prior[i];
            pmx[i]=rmx[j]; pmy[i]=rmy[j]; pmz[i]=rmz[j]; pcc[i]=rcc[j];
        } else { pmx[i]=0.f; pmy[i]=0.f; pmz[i]=0.f; pcc[i]=3e37f; }
    }
    __syncthreads();

    // load PTS obj points, broadcast-pack coords
    u64 AX[PTS], AY[PTS], AZ[PTS], A2[PTS];
    float ox[PTS], oy[PTS], oz[PTS], a2s[PTS];
    {
        const int base = blockIdx.x * (MAIN_TPB * PTS) + tid;
        #pragma unroll
        for (int i = 0; i < PTS; i++) {
            const float* o = obj + ((size_t)b * N1P + base + i * MAIN_TPB) * 3;
            ox[i] = o[0]; oy[i] = o[1]; oz[i] = o[2];
            a2s[i] = fmaf(oz[i], oz[i], fmaf(oy[i], oy[i], ox[i]*ox[i]));
            AX[i] = bcast2(ox[i]); AY[i] = bcast2(oy[i]); AZ[i] = bcast2(oz[i]);
            A2[i] = bcast2(a2s[i]);
        }
    }

    float dg0[PTS], dg1[PTS], dp0[PTS], dp1[PTS];
    int   kl[PTS], kh[PTS];
    #pragma unroll
    for (int i = 0; i < PTS; i++) {
        dg0[i] = 3e38f; dg1[i] = 3e38f; dp0[i] = 3e38f; dp1[i] = 3e38f;
        kl[i] = 0x7FFFFFFF; kh[i] = 0x7FFFFFFF;
    }

    // ---- gt sweep (a2 folded out; min only) ----
    #pragma unroll 1
    for (int t = 0; t < VP; t += 4) {
        ulonglong2 X = *(const ulonglong2*)(tmx + t);
        ulonglong2 Y = *(const ulonglong2*)(tmy + t);
        ulonglong2 Z = *(const ulonglong2*)(tmz + t);
        ulonglong2 C = *(const ulonglong2*)(tcc + t);
        #pragma unroll
        for (int i = 0; i < PTS; i++) {
            u64 d2 = ffma2(AZ[i], Z.x, ffma2(AY[i], Y.x, ffma2(AX[i], X.x, C.x)));
            float lo, hi; unpack2f(d2, lo, hi);
            dg0[i] = fminf(dg0[i], lo); dg1[i] = fminf(dg1[i], hi);
            d2 = ffma2(AZ[i], Z.y, ffma2(AY[i], Y.y, ffma2(AX[i], X.y, C.y)));
            unpack2f(d2, lo, hi);
            dg0[i] = fminf(dg0[i], lo); dg1[i] = fminf(dg1[i], hi);
        }
    }

    // ---- recon sweep (min+argmin via packed int key; needs a2 bias for positivity) ----
    #pragma unroll 1
    for (int t = 0; t < VP; t += 4) {
        ulonglong2 X = *(const ulonglong2*)(rmx + t);
        ulonglong2 Y = *(const ulonglong2*)(rmy + t);
        ulonglong2 Z = *(const ulonglong2*)(rmz + t);
        ulonglong2 C = *(const ulonglong2*)(rcc + t);
        #pragma unroll
        for (int i = 0; i < PTS; i++) {
            u64 d2 = ffma2(AZ[i], Z.x, ffma2(AY[i], Y.x, ffma2(AX[i], X.x, fadd2(A2[i], C.x))));
            int lo, hi; unpack2i(d2, lo, hi);
            kl[i] = min(kl[i], (lo & 0xFFFFFC00) | t);
            kh[i] = min(kh[i], (hi & 0xFFFFFC00) | (t + 1));
            d2 = ffma2(AZ[i], Z.y, ffma2(AY[i], Y.y, ffma2(AX[i], X.y, fadd2(A2[i], C.y))));
            unpack2i(d2, lo, hi);
            kl[i] = min(kl[i], (lo & 0xFFFFFC00) | (t + 2));
            kh[i] = min(kh[i], (hi & 0xFFFFFC00) | (t + 3));
        }
    }

    // ---- prior sweep (a2 folded out; min only) ----
    #pragma unroll 1
    for (int t = 0; t < PP; t += 4) {
        ulonglong2 X = *(const ulonglong2*)(pmx + t);
        ulonglong2 Y = *(const ulonglong2*)(pmy + t);
        ulonglong2 Z = *(const ulonglong2*)(pmz + t);
        ulonglong2 C = *(const ulonglong2*)(pcc + t);
        #pragma unroll
        for (int i = 0; i < PTS; i++) {
            u64 d2 = ffma2(AZ[i], Z.x, ffma2(AY[i], Y.x, ffma2(AX[i], X.x, C.x)));
            float lo, hi; unpack2f(d2, lo, hi);
            dp0[i] = fminf(dp0[i], lo); dp1[i] = fminf(dp1[i], hi);
            d2 = ffma2(AZ[i], Z.y, ffma2(AY[i], Y.y, ffma2(AX[i], X.y, C.y)));
            unpack2f(d2, lo, hi);
            dp0[i] = fminf(dp0[i], lo); dp1[i] = fminf(dp1[i], hi);
        }
    }

    // ---- per-point epilogue ----
    float cm = 0.f, pen = 0.f, npn = 0.f, cons = 0.f, gtc = 0.f;
    const float* vb = g_vn + (size_t)b * 3 * NV;
    #pragma unroll
    for (int i = 0; i < PTS; i++) {
        int K = min(kl[i], kh[i]);
        float drec = fmaxf(__int_as_float(K & 0xFFFFFC00), 0.f);
        int idx = K & 1023;
        float dgt = fmaxf(fminf(dg0[i], dg1[i]) + a2s[i], 0.f);
        float dpr = fmaxf(fminf(dp0[i], dp1[i]) + a2s[i], 0.f);
        if (drec < 1e-4f) { cm += dpr; npn += 1.f; }
        bool rc = sqrtf(drec) < 0.005f;
        bool gc = sqrtf(dgt)  < 0.005f;
        if (gc) { gtc += 1.f; if (rc) cons += 1.f; }
        float nvx = -0.5f * rmx[idx], nvy = -0.5f * rmy[idx], nvz = -0.5f * rmz[idx];
        float dot = (nvx - ox[i]) * vb[idx] + (nvy - oy[i]) * vb[NV + idx]
                  + (nvz - oz[i]) * vb[2 * NV + idx];
        if (dot > 0.f) pen += drec;
    }

    for (int off = 16; off; off >>= 1) {
        cm   += __shfl_down_sync(0xFFFFFFFFu, cm,   off);
        pen  += __shfl_down_sync(0xFFFFFFFFu, pen,  off);
        npn  += __shfl_down_sync(0xFFFFFFFFu, npn,  off);
        cons += __shfl_down_sync(0xFFFFFFFFu, cons, off);
        gtc  += __shfl_down_sync(0xFFFFFFFFu, gtc,  off);
    }
    const int wid = tid >> 5, lane = tid & 31;
    if (lane == 0) {
        s_red[wid]      = cm;   s_red[4 + wid]  = pen;
        s_red[8 + wid]  = npn;  s_red[12 + wid] = cons;
        s_red[16 + wid] = gtc;
    }
    __syncthreads();
    if (tid == 0) {
        float c = 0, p = 0, n = 0, co = 0, g = 0;
        for (int w = 0; w < 4; w++) {
            c += s_red[w]; p += s_red[4+w]; n += s_red[8+w];
            co += s_red[12+w]; g += s_red[16+w];
        }
        float* gp = g_part_main + ((size_t)b * MAIN_GX + blockIdx.x) * 5;
        gp[0] = c; gp[1] = p; gp[2] = n; gp[3] = co; gp[4] = g;
    }
}

// ================= final combine =================
__global__ void k_final(const float* __restrict__ mean, const float* __restrict__ logv,
                        const float* __restrict__ rp, const float* __restrict__ xp,
                        float* __restrict__ out) {
    __shared__ float s_red[8 * 8];
    const int tid = threadIdx.x;
    float sp = 0.f, sk = 0.f, sc = 0.f;
    float scm = 0.f, spe = 0.f, snp = 0.f, sco = 0.f, sgt = 0.f;

    for (int i = tid; i < BN * 61; i += 256) { float d = rp[i] - xp[i]; sp += d * d; }
    for (int i = tid; i < BN * 64; i += 256) {
        float m = mean[i], lv = logv[i];
        sk += 1.f + lv - m*m - expf(lv);
    }
    for (int i = tid; i < NBLK_CHAM; i += 256) sc += g_part_cham[i];
    for (int i = tid; i < NBLK_MAIN; i += 256) {
        const float* gp = g_part_main + (size_t)i * 5;
        scm += gp[0]; spe += gp[1]; snp += gp[2]; sco += gp[3]; sgt += gp[4];
    }
    for (int off = 16; off; off >>= 1) {
        sp  += __shfl_down_sync(0xFFFFFFFFu, sp,  off);
        sk  += __shfl_down_sync(0xFFFFFFFFu, sk,  off);
        sc  += __shfl_down_sync(0xFFFFFFFFu, sc,  off);
        scm += __shfl_down_sync(0xFFFFFFFFu, scm, off);
        spe += __shfl_down_sync(0xFFFFFFFFu, spe, off);
        snp += __shfl_down_sync(0xFFFFFFFFu, snp, off);
        sco += __shfl_down_sync(0xFFFFFFFFu, sco, off);
        sgt += __shfl_down_sync(0xFFFFFFFFu, sgt, off);
    }
    const int wid = tid >> 5;
    if ((tid & 31) == 0) {
        s_red[wid*8+0]=sp;  s_red[wid*8+1]=sk;  s_red[wid*8+2]=sc;  s_red[wid*8+3]=scm;
        s_red[wid*8+4]=spe; s_red[wid*8+5]=snp; s_red[wid*8+6]=sco; s_red[wid*8+7]=sgt;
    }
    __syncthreads();
    if (tid == 0) {
        float t[8] = {0,0,0,0,0,0,0,0};
        for (int w = 0; w < 8; w++)
            for (int j = 0; j < 8; j++) t[j] += s_red[w*8+j];
        double param_loss  = (double)t[0] / 64.0;
        double KLD         = -0.5 * (double)t[1] / 64.0 * 10.0;
        double recon_loss  = (double)t[2] / 64.0;
        double cmap_loss   = 3000.0 * (double)t[3] / (64.0 * (double)t[5]);
        double consistency = -5.0 * (double)t[6] / ((double)t[7] + 0.0001);
        double penetr      = 100.0 * (double)t[4] / 64.0;
        double loss = (recon_loss + KLD) + 0.1 * param_loss
                    + 1000.0 * cmap_loss + 10.0 * consistency + 10.0 * penetr;
        out[0] = (float)loss;
    }
}

extern "C" void kernel_launch(void* const* d_in, const int* in_sizes, int n_in,
                              void* d_out, int out_size) {
    const float* obj   = (const float*)d_in[0];
    const float* recon = (const float*)d_in[1];
    const float* gt    = (const float*)d_in[2];
    const float* mean  = (const float*)d_in[3];
    const float* logv  = (const float*)d_in[4];
    const float* rp    = (const float*)d_in[5];
    const float* xp    = (const float*)d_in[6];
    const int*   faces = (const int*)d_in[7];
    float* out = (float*)d_out;

    k_pre<<<BN + NBLK_CHAM, 256>>>(recon, gt, faces);
    k_main<<<dim3(MAIN_GX, BN), MAIN_TPB>>>(obj, recon, gt);
    k_final<<<1, 256>>>(mean, logv, rp, xp, out);
}

// round 5
// speedup vs baseline: 1.5277x; 1.3056x over previous
#include <cuda_runtime.h>
#include <math.h>

#define BN   64
#define N1P  8192
#define NV   778
#define VP   780      // padded to multiple of 4
#define NFC  1538
#define NP   204
#define PP   208      // padded prior count

#define PTS        4                       // obj points per thread in k_main
#define MAIN_TPB   128
#define MAIN_GX    (N1P / (MAIN_TPB * PTS))   // 16
#define NBLK_MAIN  (MAIN_GX * BN)             // 1024
#define NBLK_CHAM  (2 * BN)                   // 128 (2 directions per batch)
#define CROWS      7                          // chamfer rows per thread (7*128=896>=778)

__device__ float g_vn[BN * 3 * NV];        // per-batch SoA vertex normals
__device__ float g_part_main[NBLK_MAIN * 5];
__device__ float g_part_cham[NBLK_CHAM];

__constant__ int c_prior[NP] = {
697,698,699,700,712,713,714,715,737,738,739,740,741,743,744,745,746,748,749,750,
753,754,755,756,757,758,759,760,761,762,763,764,765,766,767,768,
46,47,48,49,164,165,166,167,194,195,223,237,238,280,281,298,301,317,320,323,
324,325,326,327,328,329,330,331,332,333,340,341,342,343,344,345,346,347,348,349,
350,351,352,353,354,355,
356,357,358,359,375,376,386,387,396,397,402,403,413,429,433,434,435,436,437,438,
439,440,441,442,443,444,452,453,454,455,456,459,460,461,462,463,464,465,466,467,
468,469,470,471,484,485,486,496,497,506,507,513,514,524,545,546,547,548,549,550,
551,552,553,555,563,564,565,566,567,570,572,573,574,575,576,577,578,
580,581,582,583,600,601,602,614,615,624,625,630,631,641,663,664,665,666,667,668,
670,672,680,681,682,683,684,686,687,688,689,690,691,692,693,694,695,
73,96,98,99,772,774,775,777};

// ---- packed f32x2 helpers (sm_103a) ----
typedef unsigned long long u64;

__device__ __forceinline__ u64 ffma2(u64 a, u64 b, u64 c) {
    u64 d;
    asm("fma.rn.f32x2 %0, %1, %2, %3;" : "=l"(d) : "l"(a), "l"(b), "l"(c));
    return d;
}
__device__ __forceinline__ u64 bcast2(float x) {
    u64 r;
    asm("mov.b64 %0, {%1, %2};" : "=l"(r) : "f"(x), "f"(x));
    return r;
}
__device__ __forceinline__ void unpack2f(u64 v, float& lo, float& hi) {
    asm("mov.b64 {%0, %1}, %2;" : "=f"(lo), "=f"(hi) : "l"(v));
}

// ================= k_pre: vertex normals only =================
__global__ __launch_bounds__(256) void k_pre(const float* __restrict__ recon,
                                             const int* __restrict__ faces) {
    __shared__ float sx[NV], sy[NV], sz[NV];
    __shared__ float nx[NV], ny[NV], nz[NV];
    const int b = blockIdx.x, tid = threadIdx.x;
    const float* rb = recon + (size_t)b * NV * 3;
    for (int v = tid; v < NV; v += 256) {
        sx[v] = rb[3*v+0]; sy[v] = rb[3*v+1]; sz[v] = rb[3*v+2];
        nx[v] = 0.f; ny[v] = 0.f; nz[v] = 0.f;
    }
    __syncthreads();
    for (int f = tid; f < NFC; f += 256) {
        int i0 = faces[3*f+0], i1 = faces[3*f+1], i2 = faces[3*f+2];
        float e1x = sx[i1]-sx[i0], e1y = sy[i1]-sy[i0], e1z = sz[i1]-sz[i0];
        float e2x = sx[i2]-sx[i0], e2y = sy[i2]-sy[i0], e2z = sz[i2]-sz[i0];
        float fx = e1y*e2z - e1z*e2y;
        float fy = e1z*e2x - e1x*e2z;
        float fz = e1x*e2y - e1y*e2x;
        atomicAdd(&nx[i0], fx); atomicAdd(&ny[i0], fy); atomicAdd(&nz[i0], fz);
        atomicAdd(&nx[i1], fx); atomicAdd(&ny[i1], fy); atomicAdd(&nz[i1], fz);
        atomicAdd(&nx[i2], fx); atomicAdd(&ny[i2], fy); atomicAdd(&nz[i2], fz);
    }
    __syncthreads();
    float* vb = g_vn + (size_t)b * 3 * NV;
    for (int v = tid; v < NV; v += 256) {
        float x = nx[v], y = ny[v], z = nz[v];
        float inv = 1.f / (sqrtf(x*x + y*y + z*z) + 1e-12f);
        vb[v] = x*inv; vb[NV+v] = y*inv; vb[2*NV+v] = z*inv;
    }
}

// ================= k_main: obj sweeps + chamfer tiles =================
__global__ __launch_bounds__(MAIN_TPB) void k_main(const float* __restrict__ obj,
                                                   const float* __restrict__ recon,
                                                   const float* __restrict__ gt) {
    __shared__ __align__(16) float rmx[VP], rmy[VP], rmz[VP], rcc[VP];
    __shared__ __align__(16) float tmx[VP], tmy[VP], tmz[VP], tcc[VP];
    __shared__ __align__(16) float pmx[PP], pmy[PP], pmz[PP], pcc[PP];
    __shared__ float s_red[20];

    const int b   = blockIdx.y;
    const int tid = threadIdx.x;

    if (blockIdx.x >= MAIN_GX) {
        // ---------- chamfer tile: one direction per block ----------
        const int dir = blockIdx.x - MAIN_GX;   // 0: recon->gt, 1: gt->recon
        const float* srcp = (dir ? gt : recon) + (size_t)b * NV * 3;
        const float* tgtp = (dir ? recon : gt) + (size_t)b * NV * 3;
        for (int v = tid; v < VP; v += MAIN_TPB) {
            if (v < NV) {
                float x = tgtp[3*v+0], y = tgtp[3*v+1], z = tgtp[3*v+2];
                tmx[v] = -2.f*x; tmy[v] = -2.f*y; tmz[v] = -2.f*z;
                tcc[v] = fmaf(z, z, fmaf(y, y, x*x));
            } else { tmx[v]=0.f; tmy[v]=0.f; tmz[v]=0.f; tcc[v]=3e37f; }
        }
        __syncthreads();

        u64 CAX[CROWS], CAY[CROWS], CAZ[CROWS];
        float ca2[CROWS];
        bool  cok[CROWS];
        #pragma unroll
        for (int s = 0; s < CROWS; s++) {
            int r = tid + s * MAIN_TPB;
            cok[s] = (r < NV);
            float x = 0.f, y = 0.f, z = 0.f;
            if (cok[s]) { x = srcp[3*r+0]; y = srcp[3*r+1]; z = srcp[3*r+2]; }
            ca2[s] = fmaf(z, z, fmaf(y, y, x*x));
            CAX[s] = bcast2(x); CAY[s] = bcast2(y); CAZ[s] = bcast2(z);
        }
        float cm0[CROWS], cm1[CROWS];
        #pragma unroll
        for (int s = 0; s < CROWS; s++) { cm0[s] = 3e38f; cm1[s] = 3e38f; }

        #pragma unroll 1
        for (int t = 0; t < VP; t += 4) {
            ulonglong2 X = *(const ulonglong2*)(tmx + t);
            ulonglong2 Y = *(const ulonglong2*)(tmy + t);
            ulonglong2 Z = *(const ulonglong2*)(tmz + t);
            ulonglong2 C = *(const ulonglong2*)(tcc + t);
            #pragma unroll
            for (int s = 0; s < CROWS; s++) {
                u64 d2 = ffma2(CAZ[s], Z.x, ffma2(CAY[s], Y.x, ffma2(CAX[s], X.x, C.x)));
                float lo, hi; unpack2f(d2, lo, hi);
                cm0[s] = fminf(cm0[s], lo); cm1[s] = fminf(cm1[s], hi);
                d2 = ffma2(CAZ[s], Z.y, ffma2(CAY[s], Y.y, ffma2(CAX[s], X.y, C.y)));
                unpack2f(d2, lo, hi);
                cm0[s] = fminf(cm0[s], lo); cm1[s] = fminf(cm1[s], hi);
            }
        }
        float part = 0.f;
        #pragma unroll
        for (int s = 0; s < CROWS; s++)
            if (cok[s]) part += fmaxf(fminf(cm0[s], cm1[s]) + ca2[s], 0.f);

        for (int off = 16; off; off >>= 1) part += __shfl_down_sync(0xFFFFFFFFu, part, off);
        if ((tid & 31) == 0) s_red[tid >> 5] = part;
        __syncthreads();
        if (tid == 0) {
            float t = s_red[0] + s_red[1] + s_red[2] + s_red[3];
            g_part_cham[b * 2 + dir] = t;
        }
        return;
    }

    // ---------- main tile ----------
    const float* rb = recon + (size_t)b * NV * 3;
    const float* gb = gt    + (size_t)b * NV * 3;
    for (int v = tid; v < VP; v += MAIN_TPB) {
        if (v < NV) {
            float x = rb[3*v+0], y = rb[3*v+1], z = rb[3*v+2];
            rmx[v] = -2.f*x; rmy[v] = -2.f*y; rmz[v] = -2.f*z;
            rcc[v] = fmaf(z, z, fmaf(y, y, x*x));
            x = gb[3*v+0]; y = gb[3*v+1]; z = gb[3*v+2];
            tmx[v] = -2.f*x; tmy[v] = -2.f*y; tmz[v] = -2.f*z;
            tcc[v] = fmaf(z, z, fmaf(y, y, x*x));
        } else {
            rmx[v]=0.f; rmy[v]=0.f; rmz[v]=0.f; rcc[v]=3e37f;
            tmx[v]=0.f; tmy[v]=0.f; tmz[v]=0.f; tcc[v]=3e37f;
        }
    }
    __syncthreads();
    for (int i = tid; i < PP; i += MAIN_TPB) {
        if (i < NP) {
            int j = c_prior[i];
            pmx[i]=rmx[j]; pmy[i]=rmy[j]; pmz[i]=rmz[j]; pcc[i]=rcc[j];
        } else { pmx[i]=0.f; pmy[i]=0.f; pmz[i]=0.f; pcc[i]=3e37f; }
    }
    __syncthreads();

    u64 AX[PTS], AY[PTS], AZ[PTS];
    float ox[PTS], oy[PTS], oz[PTS], a2s[PTS];
    {
        const int base = blockIdx.x * (MAIN_TPB * PTS) + tid;
        #pragma unroll
        for (int i = 0; i < PTS; i++) {
            const float* o = obj + ((size_t)b * N1P + base + i * MAIN_TPB) * 3;
            ox[i] = o[0]; oy[i] = o[1]; oz[i] = o[2];
            a2s[i] = fmaf(oz[i], oz[i], fmaf(oy[i], oy[i], ox[i]*ox[i]));
            AX[i] = bcast2(ox[i]); AY[i] = bcast2(oy[i]); AZ[i] = bcast2(oz[i]);
        }
    }

    float dg0[PTS], dg1[PTS], dp0[PTS], dp1[PTS];
    float mr[PTS];
    int   bt[PTS];
    #pragma unroll
    for (int i = 0; i < PTS; i++) {
        dg0[i] = 3e38f; dg1[i] = 3e38f; dp0[i] = 3e38f; dp1[i] = 3e38f;
        mr[i] = 3e38f; bt[i] = 0;
    }

    // ---- gt sweep (a2 folded out; min only) ----
    #pragma unroll 2
    for (int t = 0; t < VP; t += 4) {
        ulonglong2 X = *(const ulonglong2*)(tmx + t);
        ulonglong2 Y = *(const ulonglong2*)(tmy + t);
        ulonglong2 Z = *(const ulonglong2*)(tmz + t);
        ulonglong2 C = *(const ulonglong2*)(tcc + t);
        #pragma unroll
        for (int i = 0; i < PTS; i++) {
            u64 d2 = ffma2(AZ[i], Z.x, ffma2(AY[i], Y.x, ffma2(AX[i], X.x, C.x)));
            float lo, hi; unpack2f(d2, lo, hi);
            dg0[i] = fminf(dg0[i], lo); dg1[i] = fminf(dg1[i], hi);
            d2 = ffma2(AZ[i], Z.y, ffma2(AY[i], Y.y, ffma2(AX[i], X.y, C.y)));
            unpack2f(d2, lo, hi);
            dg0[i] = fminf(dg0[i], lo); dg1[i] = fminf(dg1[i], hi);
        }
    }

    // ---- recon sweep: min + winning-group tracking (exact, no key packing) ----
    #pragma unroll 2
    for (int t = 0; t < VP; t += 4) {
        ulonglong2 X = *(const ulonglong2*)(rmx + t);
        ulonglong2 Y = *(const ulonglong2*)(rmy + t);
        ulonglong2 Z = *(const ulonglong2*)(rmz + t);
        ulonglong2 C = *(const ulonglong2*)(rcc + t);
        #pragma unroll
        for (int i = 0; i < PTS; i++) {
            u64 d2 = ffma2(AZ[i], Z.x, ffma2(AY[i], Y.x, ffma2(AX[i], X.x, C.x)));
            float lo1, hi1; unpack2f(d2, lo1, hi1);
            d2 = ffma2(AZ[i], Z.y, ffma2(AY[i], Y.y, ffma2(AX[i], X.y, C.y)));
            float lo2, hi2; unpack2f(d2, lo2, hi2);
            float h = fminf(fminf(lo1, hi1), fminf(lo2, hi2));
            bool c = h < mr[i];
            mr[i] = fminf(mr[i], h);
            bt[i] = c ? t : bt[i];
        }
    }

    // ---- prior sweep (a2 folded out; min only) ----
    #pragma unroll 2
    for (int t = 0; t < PP; t += 4) {
        ulonglong2 X = *(const ulonglong2*)(pmx + t);
        ulonglong2 Y = *(const ulonglong2*)(pmy + t);
        ulonglong2 Z = *(const ulonglong2*)(pmz + t);
        ulonglong2 C = *(const ulonglong2*)(pcc + t);
        #pragma unroll
        for (int i = 0; i < PTS; i++) {
            u64 d2 = ffma2(AZ[i], Z.x, ffma2(AY[i], Y.x, ffma2(AX[i], X.x, C.x)));
            float lo, hi; unpack2f(d2, lo, hi);
            dp0[i] = fminf(dp0[i], lo); dp1[i] = fminf(dp1[i], hi);
            d2 = ffma2(AZ[i], Z.y, ffma2(AY[i], Y.y, ffma2(AX[i], X.y, C.y)));
            unpack2f(d2, lo, hi);
            dp0[i] = fminf(dp0[i], lo); dp1[i] = fminf(dp1[i], hi);
        }
    }

    // ---- per-point epilogue: rescan winning group for exact argmin ----
    float cm = 0.f, pen = 0.f, npn = 0.f, cons = 0.f, gtc = 0.f;
    const float* vb = g_vn + (size_t)b * 3 * NV;
    #pragma unroll
    for (int i = 0; i < PTS; i++) {
        const int t = bt[i];
        const float m = mr[i];
        int idx = t;
        // reverse scan: smallest matching j wins (first-occurrence semantics)
        #pragma unroll
        for (int jj = 3; jj >= 0; jj--) {
            int j = t + jj;
            float dj = fmaf(oz[i], rmz[j], fmaf(oy[i], rmy[j], fmaf(ox[i], rmx[j], rcc[j])));
            if (dj == m) idx = j;
        }
        float drec = fmaxf(m + a2s[i], 0.f);
        float dgt  = fmaxf(fminf(dg0[i], dg1[i]) + a2s[i], 0.f);
        float dpr  = fmaxf(fminf(dp0[i], dp1[i]) + a2s[i], 0.f);
        if (drec < 1e-4f) { cm += dpr; npn += 1.f; }
        bool rc = sqrtf(drec) < 0.005f;
        bool gc = sqrtf(dgt)  < 0.005f;
        if (gc) { gtc += 1.f; if (rc) cons += 1.f; }
        float nvx = -0.5f * rmx[idx], nvy = -0.5f * rmy[idx], nvz = -0.5f * rmz[idx];
        float dot = (nvx - ox[i]) * vb[idx] + (nvy - oy[i]) * vb[NV + idx]
                  + (nvz - oz[i]) * vb[2 * NV + idx];
        if (dot > 0.f) pen += drec;
    }

    for (int off = 16; off; off >>= 1) {
        cm   += __shfl_down_sync(0xFFFFFFFFu, cm,   off);
        pen  += __shfl_down_sync(0xFFFFFFFFu, pen,  off);
        npn  += __shfl_down_sync(0xFFFFFFFFu, npn,  off);
        cons += __shfl_down_sync(0xFFFFFFFFu, cons, off);
        gtc  += __shfl_down_sync(0xFFFFFFFFu, gtc,  off);
    }
    const int wid = tid >> 5, lane = tid & 31;
    if (lane == 0) {
        s_red[wid]      = cm;   s_red[4 + wid]  = pen;
        s_red[8 + wid]  = npn;  s_red[12 + wid] = cons;
        s_red[16 + wid] = gtc;
    }
    __syncthreads();
    if (tid == 0) {
        float c = 0, p = 0, n = 0, co = 0, g = 0;
        for (int w = 0; w < 4; w++) {
            c += s_red[w]; p += s_red[4+w]; n += s_red[8+w];
            co += s_red[12+w]; g += s_red[16+w];
        }
        float* gp = g_part_main + ((size_t)b * MAIN_GX + blockIdx.x) * 5;
        gp[0] = c; gp[1] = p; gp[2] = n; gp[3] = co; gp[4] = g;
    }
}

// ================= final combine =================
__global__ void k_final(const float* __restrict__ mean, const float* __restrict__ logv,
                        const float* __restrict__ rp, const float* __restrict__ xp,
                        float* __restrict__ out) {
    __shared__ float s_red[8 * 8];
    const int tid = threadIdx.x;
    float sp = 0.f, sk = 0.f, sc = 0.f;
    float scm = 0.f, spe = 0.f, snp = 0.f, sco = 0.f, sgt = 0.f;

    for (int i = tid; i < BN * 61; i += 256) { float d = rp[i] - xp[i]; sp += d * d; }
    for (int i = tid; i < BN * 64; i += 256) {
        float m = mean[i], lv = logv[i];
        sk += 1.f + lv - m*m - expf(lv);
    }
    for (int i = tid; i < NBLK_CHAM; i += 256) sc += g_part_cham[i];
    for (int i = tid; i < NBLK_MAIN; i += 256) {
        const float* gp = g_part_main + (size_t)i * 5;
        scm += gp[0]; spe += gp[1]; snp += gp[2]; sco += gp[3]; sgt += gp[4];
    }
    for (int off = 16; off; off >>= 1) {
        sp  += __shfl_down_sync(0xFFFFFFFFu, sp,  off);
        sk  += __shfl_down_sync(0xFFFFFFFFu, sk,  off);
        sc  += __shfl_down_sync(0xFFFFFFFFu, sc,  off);
        scm += __shfl_down_sync(0xFFFFFFFFu, scm, off);
        spe += __shfl_down_sync(0xFFFFFFFFu, spe, off);
        snp += __shfl_down_sync(0xFFFFFFFFu, snp, off);
        sco += __shfl_down_sync(0xFFFFFFFFu, sco, off);
        sgt += __shfl_down_sync(0xFFFFFFFFu, sgt, off);
    }
    const int wid = tid >> 5;
    if ((tid & 31) == 0) {
        s_red[wid*8+0]=sp;  s_red[wid*8+1]=sk;  s_red[wid*8+2]=sc;  s_red[wid*8+3]=scm;
        s_red[wid*8+4]=spe; s_red[wid*8+5]=snp; s_red[wid*8+6]=sco; s_red[wid*8+7]=sgt;
    }
    __syncthreads();
    if (tid == 0) {
        float t[8] = {0,0,0,0,0,0,0,0};
        for (int w = 0; w < 8; w++)
            for (int j = 0; j < 8; j++) t[j] += s_red[w*8+j];
        double param_loss  = (double)t[0] / 64.0;
        double KLD         = -0.5 * (double)t[1] / 64.0 * 10.0;
        double recon_loss  = (double)t[2] / 64.0;
        double cmap_loss   = 3000.0 * (double)t[3] / (64.0 * (double)t[5]);
        double consistency = -5.0 * (double)t[6] / ((double)t[7] + 0.0001);
        double penetr      = 100.0 * (double)t[4] / 64.0;
        double loss = (recon_loss + KLD) + 0.1 * param_loss
                    + 1000.0 * cmap_loss + 10.0 * consistency + 10.0 * penetr;
        out[0] = (float)loss;
    }
}

extern "C" void kernel_launch(void* const* d_in, const int* in_sizes, int n_in,
                              void* d_out, int out_size) {
    const float* obj   = (const float*)d_in[0];
    const float* recon = (const float*)d_in[1];
    const float* gt    = (const float*)d_in[2];
    const float* mean  = (const float*)d_in[3];
    const float* logv  = (const float*)d_in[4];
    const float* rp    = (const float*)d_in[5];
    const float* xp    = (const float*)d_in[6];
    const int*   faces = (const int*)d_in[7];
    float* out = (float*)d_out;

    k_pre<<<BN, 256>>>(recon, faces);
    k_main<<<dim3(MAIN_GX + 2, BN), MAIN_TPB>>>(obj, recon, gt);
    k_final<<<1, 256>>>(mean, logv, rp, xp, out);
}

// round 6
// speedup vs baseline: 1.6252x; 1.0638x over previous
#include <cuda_runtime.h>
#include <math.h>

#define BN   64
#define N1P  8192
#define NV   778
#define VP   780      // padded to multiple of 4
#define NFC  1538
#define NP   204
#define PP   208      // padded prior count

#define PTS        4
#define TPB        128
#define MAIN_GX    16                      // 16 main tiles per batch (128*4*16=8192)
#define NTILE_NORM BN                      // 64
#define NTILE_MAIN (MAIN_GX * BN)          // 1024
#define NTILE_CHAM (2 * BN)                // 128 (per-direction)
#define NTILES     (NTILE_NORM + NTILE_MAIN + NTILE_CHAM)   // 1216
#define NBLOCKS    (148 * 4)               // 592, co-resident by construction
#define CROWS      7                       // chamfer rows per thread (7*128>=778)

__device__ float g_vn[BN * 3 * NV];
__device__ float g_part_main[NTILE_MAIN * 5];
__device__ float g_part_cham[NTILE_CHAM];
__device__ int   g_done = 0;               // normals-complete counter (reset by k_final)

__constant__ int c_prior[NP] = {
697,698,699,700,712,713,714,715,737,738,739,740,741,743,744,745,746,748,749,750,
753,754,755,756,757,758,759,760,761,762,763,764,765,766,767,768,
46,47,48,49,164,165,166,167,194,195,223,237,238,280,281,298,301,317,320,323,
324,325,326,327,328,329,330,331,332,333,340,341,342,343,344,345,346,347,348,349,
350,351,352,353,354,355,
356,357,358,359,375,376,386,387,396,397,402,403,413,429,433,434,435,436,437,438,
439,440,441,442,443,444,452,453,454,455,456,459,460,461,462,463,464,465,466,467,
468,469,470,471,484,485,486,496,497,506,507,513,514,524,545,546,547,548,549,550,
551,552,553,555,563,564,565,566,567,570,572,573,574,575,576,577,578,
580,581,582,583,600,601,602,614,615,624,625,630,631,641,663,664,665,666,667,668,
670,672,680,681,682,683,684,686,687,688,689,690,691,692,693,694,695,
73,96,98,99,772,774,775,777};

typedef unsigned long long u64;

__device__ __forceinline__ u64 ffma2(u64 a, u64 b, u64 c) {
    u64 d;
    asm("fma.rn.f32x2 %0, %1, %2, %3;" : "=l"(d) : "l"(a), "l"(b), "l"(c));
    return d;
}
__device__ __forceinline__ u64 bcast2(float x) {
    u64 r;
    asm("mov.b64 %0, {%1, %2};" : "=l"(r) : "f"(x), "f"(x));
    return r;
}
__device__ __forceinline__ void unpack2f(u64 v, float& lo, float& hi) {
    asm("mov.b64 {%0, %1}, %2;" : "=f"(lo), "=f"(hi) : "l"(v));
}

// ================= persistent mega-kernel =================
__global__ __launch_bounds__(TPB, 4) void k_mega(const float* __restrict__ obj,
                                                 const float* __restrict__ recon,
                                                 const float* __restrict__ gt,
                                                 const int* __restrict__ faces) {
    // 7072 floats = 28.3KB, shared by all tile types
    __shared__ __align__(16) float S[8 * VP + 4 * PP];
    __shared__ float s_red[20];
    const int tid = threadIdx.x;

    for (int tile = blockIdx.x; tile < NTILES; tile += NBLOCKS) {
        __syncthreads();   // protect smem reuse across tiles

        if (tile < NTILE_NORM) {
            // ---------------- normals tile (batch = tile) ----------------
            const int b = tile;
            float* sx = S;          float* sy = S + NV;      float* sz = S + 2 * NV;
            float* nx = S + 3 * NV; float* ny = S + 4 * NV;  float* nz = S + 5 * NV;
            const float* rb = recon + (size_t)b * NV * 3;
            for (int v = tid; v < NV; v += TPB) {
                sx[v] = rb[3*v+0]; sy[v] = rb[3*v+1]; sz[v] = rb[3*v+2];
                nx[v] = 0.f; ny[v] = 0.f; nz[v] = 0.f;
            }
            __syncthreads();
            for (int f = tid; f < NFC; f += TPB) {
                int i0 = faces[3*f+0], i1 = faces[3*f+1], i2 = faces[3*f+2];
                float e1x = sx[i1]-sx[i0], e1y = sy[i1]-sy[i0], e1z = sz[i1]-sz[i0];
                float e2x = sx[i2]-sx[i0], e2y = sy[i2]-sy[i0], e2z = sz[i2]-sz[i0];
                float fx = e1y*e2z - e1z*e2y;
                float fy = e1z*e2x - e1x*e2z;
                float fz = e1x*e2y - e1y*e2x;
                atomicAdd(&nx[i0], fx); atomicAdd(&ny[i0], fy); atomicAdd(&nz[i0], fz);
                atomicAdd(&nx[i1], fx); atomicAdd(&ny[i1], fy); atomicAdd(&nz[i1], fz);
                atomicAdd(&nx[i2], fx); atomicAdd(&ny[i2], fy); atomicAdd(&nz[i2], fz);
            }
            __syncthreads();
            float* vb = g_vn + (size_t)b * 3 * NV;
            for (int v = tid; v < NV; v += TPB) {
                float x = nx[v], y = ny[v], z = nz[v];
                float inv = 1.f / (sqrtf(x*x + y*y + z*z) + 1e-12f);
                vb[v] = x*inv; vb[NV+v] = y*inv; vb[2*NV+v] = z*inv;
            }
            __syncthreads();
            __threadfence();           // release g_vn
            if (tid == 0) atomicAdd(&g_done, 1);
        }
        else if (tile < NTILE_NORM + NTILE_MAIN) {
            // ---------------- main tile ----------------
            const int m  = tile - NTILE_NORM;
            const int b  = m >> 4;          // /MAIN_GX
            const int xt = m & 15;
            float* rmx = S;          float* rmy = S + VP;     float* rmz = S + 2*VP; float* rcc = S + 3*VP;
            float* tmx = S + 4*VP;   float* tmy = S + 5*VP;   float* tmz = S + 6*VP; float* tcc = S + 7*VP;
            float* pmx = S + 8*VP;   float* pmy = pmx + PP;   float* pmz = pmy + PP; float* pcc = pmz + PP;

            const float* rb = recon + (size_t)b * NV * 3;
            const float* gb = gt    + (size_t)b * NV * 3;
            for (int v = tid; v < VP; v += TPB) {
                if (v < NV) {
                    float x = rb[3*v+0], y = rb[3*v+1], z = rb[3*v+2];
                    rmx[v] = -2.f*x; rmy[v] = -2.f*y; rmz[v] = -2.f*z;
                    rcc[v] = fmaf(z, z, fmaf(y, y, x*x));
                    x = gb[3*v+0]; y = gb[3*v+1]; z = gb[3*v+2];
                    tmx[v] = -2.f*x; tmy[v] = -2.f*y; tmz[v] = -2.f*z;
                    tcc[v] = fmaf(z, z, fmaf(y, y, x*x));
                } else {
                    rmx[v]=0.f; rmy[v]=0.f; rmz[v]=0.f; rcc[v]=3e37f;
                    tmx[v]=0.f; tmy[v]=0.f; tmz[v]=0.f; tcc[v]=3e37f;
                }
            }
            __syncthreads();
            for (int i = tid; i < PP; i += TPB) {
                if (i < NP) {
                    int j = c_prior[i];
                    pmx[i]=rmx[j]; pmy[i]=rmy[j]; pmz[i]=rmz[j]; pcc[i]=rcc[j];
                } else { pmx[i]=0.f; pmy[i]=0.f; pmz[i]=0.f; pcc[i]=3e37f; }
            }
            __syncthreads();

            u64 AX[PTS], AY[PTS], AZ[PTS];
            float ox[PTS], oy[PTS], oz[PTS], a2s[PTS];
            {
                const int base = xt * (TPB * PTS) + tid;
                #pragma unroll
                for (int i = 0; i < PTS; i++) {
                    const float* o = obj + ((size_t)b * N1P + base + i * TPB) * 3;
                    ox[i] = o[0]; oy[i] = o[1]; oz[i] = o[2];
                    a2s[i] = fmaf(oz[i], oz[i], fmaf(oy[i], oy[i], ox[i]*ox[i]));
                    AX[i] = bcast2(ox[i]); AY[i] = bcast2(oy[i]); AZ[i] = bcast2(oz[i]);
                }
            }

            float dg0[PTS], dg1[PTS], dp0[PTS], dp1[PTS], mr[PTS];
            int   bt[PTS];
            #pragma unroll
            for (int i = 0; i < PTS; i++) {
                dg0[i] = 3e38f; dg1[i] = 3e38f; dp0[i] = 3e38f; dp1[i] = 3e38f;
                mr[i] = 3e38f; bt[i] = 0;
            }

            // gt sweep (min only)
            #pragma unroll 2
            for (int t = 0; t < VP; t += 4) {
                ulonglong2 X = *(const ulonglong2*)(tmx + t);
                ulonglong2 Y = *(const ulonglong2*)(tmy + t);
                ulonglong2 Z = *(const ulonglong2*)(tmz + t);
                ulonglong2 C = *(const ulonglong2*)(tcc + t);
                #pragma unroll
                for (int i = 0; i < PTS; i++) {
                    u64 d2 = ffma2(AZ[i], Z.x, ffma2(AY[i], Y.x, ffma2(AX[i], X.x, C.x)));
                    float lo, hi; unpack2f(d2, lo, hi);
                    dg0[i] = fminf(dg0[i], lo); dg1[i] = fminf(dg1[i], hi);
                    d2 = ffma2(AZ[i], Z.y, ffma2(AY[i], Y.y, ffma2(AX[i], X.y, C.y)));
                    unpack2f(d2, lo, hi);
                    dg0[i] = fminf(dg0[i], lo); dg1[i] = fminf(dg1[i], hi);
                }
            }

            // recon sweep (min + winning-group tracking)
            #pragma unroll 2
            for (int t = 0; t < VP; t += 4) {
                ulonglong2 X = *(const ulonglong2*)(rmx + t);
                ulonglong2 Y = *(const ulonglong2*)(rmy + t);
                ulonglong2 Z = *(const ulonglong2*)(rmz + t);
                ulonglong2 C = *(const ulonglong2*)(rcc + t);
                #pragma unroll
                for (int i = 0; i < PTS; i++) {
                    u64 d2 = ffma2(AZ[i], Z.x, ffma2(AY[i], Y.x, ffma2(AX[i], X.x, C.x)));
                    float lo1, hi1; unpack2f(d2, lo1, hi1);
                    d2 = ffma2(AZ[i], Z.y, ffma2(AY[i], Y.y, ffma2(AX[i], X.y, C.y)));
                    float lo2, hi2; unpack2f(d2, lo2, hi2);
                    float h = fminf(fminf(lo1, hi1), fminf(lo2, hi2));
                    bool c = h < mr[i];
                    mr[i] = fminf(mr[i], h);
                    bt[i] = c ? t : bt[i];
                }
            }

            // prior sweep (min only)
            #pragma unroll 2
            for (int t = 0; t < PP; t += 4) {
                ulonglong2 X = *(const ulonglong2*)(pmx + t);
                ulonglong2 Y = *(const ulonglong2*)(pmy + t);
                ulonglong2 Z = *(const ulonglong2*)(pmz + t);
                ulonglong2 C = *(const ulonglong2*)(pcc + t);
                #pragma unroll
                for (int i = 0; i < PTS; i++) {
                    u64 d2 = ffma2(AZ[i], Z.x, ffma2(AY[i], Y.x, ffma2(AX[i], X.x, C.x)));
                    float lo, hi; unpack2f(d2, lo, hi);
                    dp0[i] = fminf(dp0[i], lo); dp1[i] = fminf(dp1[i], hi);
                    d2 = ffma2(AZ[i], Z.y, ffma2(AY[i], Y.y, ffma2(AX[i], X.y, C.y)));
                    unpack2f(d2, lo, hi);
                    dp0[i] = fminf(dp0[i], lo); dp1[i] = fminf(dp1[i], hi);
                }
            }

            // acquire g_vn (normals tiles finish long before any sweep ends)
            if (tid == 0) {
                while (*(volatile int*)&g_done < BN) { }
            }
            __syncthreads();
            __threadfence();

            float cm = 0.f, pen = 0.f, npn = 0.f, cons = 0.f, gtc = 0.f;
            const float* vb = g_vn + (size_t)b * 3 * NV;
            #pragma unroll
            for (int i = 0; i < PTS; i++) {
                const int t = bt[i];
                const float m2 = mr[i];
                int idx = t;
                #pragma unroll
                for (int jj = 3; jj >= 0; jj--) {   // reverse scan: first occurrence wins
                    int j = t + jj;
                    float dj = fmaf(oz[i], rmz[j], fmaf(oy[i], rmy[j], fmaf(ox[i], rmx[j], rcc[j])));
                    if (dj == m2) idx = j;
                }
                float drec = fmaxf(m2 + a2s[i], 0.f);
                float dgt  = fmaxf(fminf(dg0[i], dg1[i]) + a2s[i], 0.f);
                float dpr  = fmaxf(fminf(dp0[i], dp1[i]) + a2s[i], 0.f);
                if (drec < 1e-4f) { cm += dpr; npn += 1.f; }
                bool rc = sqrtf(drec) < 0.005f;
                bool gc = sqrtf(dgt)  < 0.005f;
                if (gc) { gtc += 1.f; if (rc) cons += 1.f; }
                float nvx = -0.5f * rmx[idx], nvy = -0.5f * rmy[idx], nvz = -0.5f * rmz[idx];
                float dot = (nvx - ox[i]) * __ldcg(vb + idx)
                          + (nvy - oy[i]) * __ldcg(vb + NV + idx)
                          + (nvz - oz[i]) * __ldcg(vb + 2 * NV + idx);
                if (dot > 0.f) pen += drec;
            }

            for (int off = 16; off; off >>= 1) {
                cm   += __shfl_down_sync(0xFFFFFFFFu, cm,   off);
                pen  += __shfl_down_sync(0xFFFFFFFFu, pen,  off);
                npn  += __shfl_down_sync(0xFFFFFFFFu, npn,  off);
                cons += __shfl_down_sync(0xFFFFFFFFu, cons, off);
                gtc  += __shfl_down_sync(0xFFFFFFFFu, gtc,  off);
            }
            const int wid = tid >> 5, lane = tid & 31;
            if (lane == 0) {
                s_red[wid]      = cm;   s_red[4 + wid]  = pen;
                s_red[8 + wid]  = npn;  s_red[12 + wid] = cons;
                s_red[16 + wid] = gtc;
            }
            __syncthreads();
            if (tid == 0) {
                float c = 0, p = 0, n = 0, co = 0, g = 0;
                for (int w = 0; w < 4; w++) {
                    c += s_red[w]; p += s_red[4+w]; n += s_red[8+w];
                    co += s_red[12+w]; g += s_red[16+w];
                }
                float* gp = g_part_main + (size_t)m * 5;
                gp[0] = c; gp[1] = p; gp[2] = n; gp[3] = co; gp[4] = g;
            }
        }
        else {
            // ---------------- chamfer tile (one direction) ----------------
            const int c   = tile - NTILE_NORM - NTILE_MAIN;  // 0..127
            const int b   = c >> 1;
            const int dir = c & 1;
            const float* srcp = (dir ? gt : recon) + (size_t)b * NV * 3;
            const float* tgtp = (dir ? recon : gt) + (size_t)b * NV * 3;
            float* tmx = S;        float* tmy = S + VP;
            float* tmz = S + 2*VP; float* tcc = S + 3*VP;
            for (int v = tid; v < VP; v += TPB) {
                if (v < NV) {
                    float x = tgtp[3*v+0], y = tgtp[3*v+1], z = tgtp[3*v+2];
                    tmx[v] = -2.f*x; tmy[v] = -2.f*y; tmz[v] = -2.f*z;
                    tcc[v] = fmaf(z, z, fmaf(y, y, x*x));
                } else { tmx[v]=0.f; tmy[v]=0.f; tmz[v]=0.f; tcc[v]=3e37f; }
            }
            __syncthreads();

            u64 CAX[CROWS], CAY[CROWS], CAZ[CROWS];
            float ca2[CROWS];
            bool  cok[CROWS];
            #pragma unroll
            for (int s = 0; s < CROWS; s++) {
                int r = tid + s * TPB;
                cok[s] = (r < NV);
                float x = 0.f, y = 0.f, z = 0.f;
                if (cok[s]) { x = srcp[3*r+0]; y = srcp[3*r+1]; z = srcp[3*r+2]; }
                ca2[s] = fmaf(z, z, fmaf(y, y, x*x));
                CAX[s] = bcast2(x); CAY[s] = bcast2(y); CAZ[s] = bcast2(z);
            }
            float cm0[CROWS], cm1[CROWS];
            #pragma unroll
            for (int s = 0; s < CROWS; s++) { cm0[s] = 3e38f; cm1[s] = 3e38f; }

            #pragma unroll 1
            for (int t = 0; t < VP; t += 4) {
                ulonglong2 X = *(const ulonglong2*)(tmx + t);
                ulonglong2 Y = *(const ulonglong2*)(tmy + t);
                ulonglong2 Z = *(const ulonglong2*)(tmz + t);
                ulonglong2 C = *(const ulonglong2*)(tcc + t);
                #pragma unroll
                for (int s = 0; s < CROWS; s++) {
                    u64 d2 = ffma2(CAZ[s], Z.x, ffma2(CAY[s], Y.x, ffma2(CAX[s], X.x, C.x)));
                    float lo, hi; unpack2f(d2, lo, hi);
                    cm0[s] = fminf(cm0[s], lo); cm1[s] = fminf(cm1[s], hi);
                    d2 = ffma2(CAZ[s], Z.y, ffma2(CAY[s], Y.y, ffma2(CAX[s], X.y, C.y)));
                    unpack2f(d2, lo, hi);
                    cm0[s] = fminf(cm0[s], lo); cm1[s] = fminf(cm1[s], hi);
                }
            }
            float part = 0.f;
            #pragma unroll
            for (int s = 0; s < CROWS; s++)
                if (cok[s]) part += fmaxf(fminf(cm0[s], cm1[s]) + ca2[s], 0.f);

            for (int off = 16; off; off >>= 1) part += __shfl_down_sync(0xFFFFFFFFu, part, off);
            if ((tid & 31) == 0) s_red[tid >> 5] = part;
            __syncthreads();
            if (tid == 0)
                g_part_cham[c] = s_red[0] + s_red[1] + s_red[2] + s_red[3];
        }
    }
}

// ================= final combine =================
__global__ void k_final(const float* __restrict__ mean, const float* __restrict__ logv,
                        const float* __restrict__ rp, const float* __restrict__ xp,
                        float* __restrict__ out) {
    __shared__ float s_red[8 * 8];
    const int tid = threadIdx.x;
    float sp = 0.f, sk = 0.f, sc = 0.f;
    float scm = 0.f, spe = 0.f, snp = 0.f, sco = 0.f, sgt = 0.f;

    for (int i = tid; i < BN * 61; i += 256) { float d = rp[i] - xp[i]; sp += d * d; }
    for (int i = tid; i < BN * 64; i += 256) {
        float m = mean[i], lv = logv[i];
        sk += 1.f + lv - m*m - expf(lv);
    }
    for (int i = tid; i < NTILE_CHAM; i += 256) sc += g_part_cham[i];
    for (int i = tid; i < NTILE_MAIN; i += 256) {
        const float* gp = g_part_main + (size_t)i * 5;
        scm += gp[0]; spe += gp[1]; snp += gp[2]; sco += gp[3]; sgt += gp[4];
    }
    for (int off = 16; off; off >>= 1) {
        sp  += __shfl_down_sync(0xFFFFFFFFu, sp,  off);
        sk  += __shfl_down_sync(0xFFFFFFFFu, sk,  off);
        sc  += __shfl_down_sync(0xFFFFFFFFu, sc,  off);
        scm += __shfl_down_sync(0xFFFFFFFFu, scm, off);
        spe += __shfl_down_sync(0xFFFFFFFFu, spe, off);
        snp += __shfl_down_sync(0xFFFFFFFFu, snp, off);
        sco += __shfl_down_sync(0xFFFFFFFFu, sco, off);
        sgt += __shfl_down_sync(0xFFFFFFFFu, sgt, off);
    }
    const int wid = tid >> 5;
    if ((tid & 31) == 0) {
        s_red[wid*8+0]=sp;  s_red[wid*8+1]=sk;  s_red[wid*8+2]=sc;  s_red[wid*8+3]=scm;
        s_red[wid*8+4]=spe; s_red[wid*8+5]=snp; s_red[wid*8+6]=sco; s_red[wid*8+7]=sgt;
    }
    __syncthreads();
    if (tid == 0) {
        float t[8] = {0,0,0,0,0,0,0,0};
        for (int w = 0; w < 8; w++)
            for (int j = 0; j < 8; j++) t[j] += s_red[w*8+j];
        double param_loss  = (double)t[0] / 64.0;
        double KLD         = -0.5 * (double)t[1] / 64.0 * 10.0;
        double recon_loss  = (double)t[2] / 64.0;
        double cmap_loss   = 3000.0 * (double)t[3] / (64.0 * (double)t[5]);
        double consistency = -5.0 * (double)t[6] / ((double)t[7] + 0.0001);
        double penetr      = 100.0 * (double)t[4] / 64.0;
        double loss = (recon_loss + KLD) + 0.1 * param_loss
                    + 1000.0 * cmap_loss + 10.0 * consistency + 10.0 * penetr;
        out[0] = (float)loss;
        g_done = 0;    // reset for next graph replay (deterministic)
    }
}

extern "C" void kernel_launch(void* const* d_in, const int* in_sizes, int n_in,
                              void* d_out, int out_size) {
    const float* obj   = (const float*)d_in[0];
    const float* recon = (const float*)d_in[1];
    const float* gt    = (const float*)d_in[2];
    const float* mean  = (const float*)d_in[3];
    const float* logv  = (const float*)d_in[4];
    const float* rp    = (const float*)d_in[5];
    const float* xp    = (const float*)d_in[6];
    const int*   faces = (const int*)d_in[7];
    float* out = (float*)d_out;

    k_mega<<<NBLOCKS, TPB>>>(obj, recon, gt, faces);
    k_final<<<1, 256>>>(mean, logv, rp, xp, out);
}

// round 7
// speedup vs baseline: 1.6913x; 1.0407x over previous
#include <cuda_runtime.h>
#include <math.h>

#define BN   64
#define N1P  8192
#define NV   778
#define VP   780      // padded to multiple of 4
#define NFC  1538
#define NP   204      // prior subset size (204 = 4*51)

#define PTS        4
#define TPB        128
#define MAIN_GX    16                      // 16 main tiles per batch
#define NTILE_MAIN (MAIN_GX * BN)          // 1024
#define NTILE_CHAM (2 * BN)                // 128
// tickets: 0 = slot-map build, [1,65) normals, [65,1089) main, [1089,1217) chamfer
#define T_NORM     1
#define T_MAIN     (T_NORM + BN)           // 65
#define T_CHAM     (T_MAIN + NTILE_MAIN)   // 1089
#define NTILES     (T_CHAM + NTILE_CHAM)   // 1217
#define NBLOCKS    (148 * 4)               // 592, all co-resident

__device__ float g_vn[BN * 3 * NV];
__device__ float g_part_main[NTILE_MAIN * 5];
__device__ float g_part_cham[NTILE_CHAM];
__device__ int   g_slot2orig[VP];
__device__ int   g_ticket = 0;
__device__ int   g_done = 0;       // normals completed
__device__ int   g_mapdone = 0;    // slot map ready
__device__ int   g_fin = 0;        // blocks finished

// PRIOR_IDX sorted ascending (204 entries)
__constant__ int c_prior_sorted[NP] = {
46,47,48,49,73,96,98,99,
164,165,166,167,194,195,223,237,238,280,281,298,301,317,320,
323,324,325,326,327,328,329,330,331,332,333,
340,341,342,343,344,345,346,347,348,349,350,351,352,353,354,355,
356,357,358,359,375,376,386,387,396,397,402,403,413,429,
433,434,435,436,437,438,439,440,441,442,443,444,
452,453,454,455,456,459,460,461,462,463,464,465,466,467,
468,469,470,471,484,485,486,496,497,506,507,513,514,524,
545,546,547,548,549,550,551,552,553,555,
563,564,565,566,567,570,572,573,574,575,576,577,578,
580,581,582,583,600,601,602,614,615,624,625,630,631,641,
663,664,665,666,667,668,670,672,
680,681,682,683,684,686,687,688,689,690,691,692,693,694,695,
697,698,699,700,712,713,714,715,
737,738,739,740,741,743,744,745,746,748,749,750,
753,754,755,756,757,758,759,760,761,762,763,764,765,766,767,768,
772,774,775,777};

typedef unsigned long long u64;

__device__ __forceinline__ u64 ffma2(u64 a, u64 b, u64 c) {
    u64 d;
    asm("fma.rn.f32x2 %0, %1, %2, %3;" : "=l"(d) : "l"(a), "l"(b), "l"(c));
    return d;
}
__device__ __forceinline__ u64 bcast2(float x) {
    u64 r;
    asm("mov.b64 %0, {%1, %2};" : "=l"(r) : "f"(x), "f"(x));
    return r;
}
__device__ __forceinline__ void unpack2f(u64 v, float& lo, float& hi) {
    asm("mov.b64 {%0, %1}, %2;" : "=f"(lo), "=f"(hi) : "l"(v));
}

__global__ __launch_bounds__(TPB, 4) void k_mega(const float* __restrict__ obj,
                                                 const float* __restrict__ recon,
                                                 const float* __restrict__ gt,
                                                 const int* __restrict__ faces,
                                                 const float* __restrict__ mean,
                                                 const float* __restrict__ logv,
                                                 const float* __restrict__ rp,
                                                 const float* __restrict__ xp,
                                                 float* __restrict__ out) {
    __shared__ __align__(16) float S[8 * VP];   // 24.4KB, reused by all tile types
    __shared__ int   s2o[VP];
    __shared__ float s_red[20];
    __shared__ int   s_tile;
    const int tid = threadIdx.x;

    while (true) {
        __syncthreads();   // protect smem reuse + s_tile
        if (tid == 0) s_tile = atomicAdd(&g_ticket, 1);
        __syncthreads();
        const int tile = s_tile;
        if (tile >= NTILES) break;

        if (tile == 0) {
            // ---------------- slot-map build ----------------
            for (int j = tid; j < NV; j += TPB) {
                int lo = 0, hi = NP;                       // lower_bound
                while (lo < hi) { int mid = (lo + hi) >> 1;
                    if (c_prior_sorted[mid] < j) lo = mid + 1; else hi = mid; }
                bool member = (lo < NP) && (c_prior_sorted[lo] == j);
                int slot = member ? lo : (NP + j - lo);
                g_slot2orig[slot] = j;
            }
            for (int s = NV + tid; s < VP; s += TPB) g_slot2orig[s] = -1;
            __syncthreads();
            __threadfence();
            if (tid == 0) atomicExch(&g_mapdone, 1);
        }
        else if (tile < T_MAIN) {
            // ---------------- normals tile ----------------
            const int b = tile - T_NORM;
            float* sx = S;          float* sy = S + NV;      float* sz = S + 2 * NV;
            float* nx = S + 3 * NV; float* ny = S + 4 * NV;  float* nz = S + 5 * NV;
            const float* rb = recon + (size_t)b * NV * 3;
            for (int v = tid; v < NV; v += TPB) {
                sx[v] = rb[3*v+0]; sy[v] = rb[3*v+1]; sz[v] = rb[3*v+2];
                nx[v] = 0.f; ny[v] = 0.f; nz[v] = 0.f;
            }
            __syncthreads();
            for (int f = tid; f < NFC; f += TPB) {
                int i0 = faces[3*f+0], i1 = faces[3*f+1], i2 = faces[3*f+2];
                float e1x = sx[i1]-sx[i0], e1y = sy[i1]-sy[i0], e1z = sz[i1]-sz[i0];
                float e2x = sx[i2]-sx[i0], e2y = sy[i2]-sy[i0], e2z = sz[i2]-sz[i0];
                float fx = e1y*e2z - e1z*e2y;
                float fy = e1z*e2x - e1x*e2z;
                float fz = e1x*e2y - e1y*e2x;
                atomicAdd(&nx[i0], fx); atomicAdd(&ny[i0], fy); atomicAdd(&nz[i0], fz);
                atomicAdd(&nx[i1], fx); atomicAdd(&ny[i1], fy); atomicAdd(&nz[i1], fz);
                atomicAdd(&nx[i2], fx); atomicAdd(&ny[i2], fy); atomicAdd(&nz[i2], fz);
            }
            __syncthreads();
            float* vb = g_vn + (size_t)b * 3 * NV;
            for (int v = tid; v < NV; v += TPB) {
                float x = nx[v], y = ny[v], z = nz[v];
                float inv = 1.f / (sqrtf(x*x + y*y + z*z) + 1e-12f);
                vb[v] = x*inv; vb[NV+v] = y*inv; vb[2*NV+v] = z*inv;
            }
            __syncthreads();
            __threadfence();
            if (tid == 0) atomicAdd(&g_done, 1);
        }
        else if (tile < T_CHAM) {
            // ---------------- main tile ----------------
            const int m  = tile - T_MAIN;
            const int b  = m >> 4;
            const int xt = m & 15;
            float* rmx = S;          float* rmy = S + VP;   float* rmz = S + 2*VP; float* rcc = S + 3*VP;
            float* tmx = S + 4*VP;   float* tmy = S + 5*VP; float* tmz = S + 6*VP; float* tcc = S + 7*VP;

            // wait for slot map (ready within ~2us of launch)
            if (tid == 0) { while (*(volatile int*)&g_mapdone == 0) { } }
            __syncthreads();

            const float* rb = recon + (size_t)b * NV * 3;
            const float* gb = gt    + (size_t)b * NV * 3;
            for (int v = tid; v < VP; v += TPB) {
                int orig = g_slot2orig[v];
                s2o[v] = orig < 0 ? 0 : orig;
                if (orig >= 0) {
                    float x = rb[3*orig+0], y = rb[3*orig+1], z = rb[3*orig+2];
                    rmx[v] = -2.f*x; rmy[v] = -2.f*y; rmz[v] = -2.f*z;
                    rcc[v] = fmaf(z, z, fmaf(y, y, x*x));
                } else {
                    rmx[v]=0.f; rmy[v]=0.f; rmz[v]=0.f; rcc[v]=3e37f;
                }
                if (v < NV) {
                    float x = gb[3*v+0], y = gb[3*v+1], z = gb[3*v+2];
                    tmx[v] = -2.f*x; tmy[v] = -2.f*y; tmz[v] = -2.f*z;
                    tcc[v] = fmaf(z, z, fmaf(y, y, x*x));
                } else {
                    tmx[v]=0.f; tmy[v]=0.f; tmz[v]=0.f; tcc[v]=3e37f;
                }
            }
            __syncthreads();

            u64 AX[PTS], AY[PTS], AZ[PTS];
            float ox[PTS], oy[PTS], oz[PTS], a2s[PTS];
            {
                const int base = xt * (TPB * PTS) + tid;
                #pragma unroll
                for (int i = 0; i < PTS; i++) {
                    const float* o = obj + ((size_t)b * N1P + base + i * TPB) * 3;
                    ox[i] = o[0]; oy[i] = o[1]; oz[i] = o[2];
                    a2s[i] = fmaf(oz[i], oz[i], fmaf(oy[i], oy[i], ox[i]*ox[i]));
                    AX[i] = bcast2(ox[i]); AY[i] = bcast2(oy[i]); AZ[i] = bcast2(oz[i]);
                }
            }

            float dg0[PTS], dg1[PTS], mA[PTS], mr[PTS];
            int   bt[PTS];
            #pragma unroll
            for (int i = 0; i < PTS; i++) {
                dg0[i] = 3e38f; dg1[i] = 3e38f; mA[i] = 3e38f; mr[i] = 3e38f; bt[i] = 0;
            }

            // gt sweep (min only)
            #pragma unroll 2
            for (int t = 0; t < VP; t += 4) {
                ulonglong2 X = *(const ulonglong2*)(tmx + t);
                ulonglong2 Y = *(const ulonglong2*)(tmy + t);
                ulonglong2 Z = *(const ulonglong2*)(tmz + t);
                ulonglong2 C = *(const ulonglong2*)(tcc + t);
                #pragma unroll
                for (int i = 0; i < PTS; i++) {
                    u64 d2 = ffma2(AZ[i], Z.x, ffma2(AY[i], Y.x, ffma2(AX[i], X.x, C.x)));
                    float lo, hi; unpack2f(d2, lo, hi);
                    dg0[i] = fminf(dg0[i], lo); dg1[i] = fminf(dg1[i], hi);
                    d2 = ffma2(AZ[i], Z.y, ffma2(AY[i], Y.y, ffma2(AX[i], X.y, C.y)));
                    unpack2f(d2, lo, hi);
                    dg0[i] = fminf(dg0[i], lo); dg1[i] = fminf(dg1[i], hi);
                }
            }

            // recon sweep, segment A: prior slots [0,204) — track prior min too
            #pragma unroll 2
            for (int t = 0; t < NP; t += 4) {
                ulonglong2 X = *(const ulonglong2*)(rmx + t);
                ulonglong2 Y = *(const ulonglong2*)(rmy + t);
                ulonglong2 Z = *(const ulonglong2*)(rmz + t);
                ulonglong2 C = *(const ulonglong2*)(rcc + t);
                #pragma unroll
                for (int i = 0; i < PTS; i++) {
                    u64 d2 = ffma2(AZ[i], Z.x, ffma2(AY[i], Y.x, ffma2(AX[i], X.x, C.x)));
                    float lo1, hi1; unpack2f(d2, lo1, hi1);
                    d2 = ffma2(AZ[i], Z.y, ffma2(AY[i], Y.y, ffma2(AX[i], X.y, C.y)));
                    float lo2, hi2; unpack2f(d2, lo2, hi2);
                    float h = fminf(fminf(lo1, hi1), fminf(lo2, hi2));
                    mA[i] = fminf(mA[i], h);
                    bool c = h < mr[i];
                    mr[i] = fminf(mr[i], h);
                    bt[i] = c ? t : bt[i];
                }
            }
            // segment B: remaining slots [204,VP)
            #pragma unroll 2
            for (int t = NP; t < VP; t += 4) {
                ulonglong2 X = *(const ulonglong2*)(rmx + t);
                ulonglong2 Y = *(const ulonglong2*)(rmy + t);
                ulonglong2 Z = *(const ulonglong2*)(rmz + t);
                ulonglong2 C = *(const ulonglong2*)(rcc + t);
                #pragma unroll
                for (int i = 0; i < PTS; i++) {
                    u64 d2 = ffma2(AZ[i], Z.x, ffma2(AY[i], Y.x, ffma2(AX[i], X.x, C.x)));
                    float lo1, hi1; unpack2f(d2, lo1, hi1);
                    d2 = ffma2(AZ[i], Z.y, ffma2(AY[i], Y.y, ffma2(AX[i], X.y, C.y)));
                    float lo2, hi2; unpack2f(d2, lo2, hi2);
                    float h = fminf(fminf(lo1, hi1), fminf(lo2, hi2));
                    bool c = h < mr[i];
                    mr[i] = fminf(mr[i], h);
                    bt[i] = c ? t : bt[i];
                }
            }

            // wait for normals (done long ago)
            if (tid == 0) { while (*(volatile int*)&g_done < BN) { } }
            __syncthreads();
            __threadfence();

            float cm = 0.f, pen = 0.f, npn = 0.f, cons = 0.f, gtc = 0.f;
            const float* vb = g_vn + (size_t)b * 3 * NV;
            #pragma unroll
            for (int i = 0; i < PTS; i++) {
                const int t = bt[i];
                const float m2 = mr[i];
                int slot = t;
                #pragma unroll
                for (int jj = 3; jj >= 0; jj--) {   // reverse scan: earliest slot wins
                    int j = t + jj;
                    float dj = fmaf(oz[i], rmz[j], fmaf(oy[i], rmy[j], fmaf(ox[i], rmx[j], rcc[j])));
                    if (dj == m2) slot = j;
                }
                const int idx = s2o[slot];
                float drec = fmaxf(m2 + a2s[i], 0.f);
                float dgt  = fmaxf(fminf(dg0[i], dg1[i]) + a2s[i], 0.f);
                float dpr  = fmaxf(mA[i] + a2s[i], 0.f);
                if (drec < 1e-4f) { cm += dpr; npn += 1.f; }
                bool rc = sqrtf(drec) < 0.005f;
                bool gc = sqrtf(dgt)  < 0.005f;
                if (gc) { gtc += 1.f; if (rc) cons += 1.f; }
                float nvx = -0.5f * rmx[slot], nvy = -0.5f * rmy[slot], nvz = -0.5f * rmz[slot];
                float dot = (nvx - ox[i]) * __ldcg(vb + idx)
                          + (nvy - oy[i]) * __ldcg(vb + NV + idx)
                          + (nvz - oz[i]) * __ldcg(vb + 2 * NV + idx);
                if (dot > 0.f) pen += drec;
            }

            for (int off = 16; off; off >>= 1) {
                cm   += __shfl_down_sync(0xFFFFFFFFu, cm,   off);
                pen  += __shfl_down_sync(0xFFFFFFFFu, pen,  off);
                npn  += __shfl_down_sync(0xFFFFFFFFu, npn,  off);
                cons += __shfl_down_sync(0xFFFFFFFFu, cons, off);
                gtc  += __shfl_down_sync(0xFFFFFFFFu, gtc,  off);
            }
            const int wid = tid >> 5, lane = tid & 31;
            if (lane == 0) {
                s_red[wid]      = cm;   s_red[4 + wid]  = pen;
                s_red[8 + wid]  = npn;  s_red[12 + wid] = cons;
                s_red[16 + wid] = gtc;
            }
            __syncthreads();
            if (tid == 0) {
                float c = 0, p = 0, n = 0, co = 0, g = 0;
                for (int w = 0; w < 4; w++) {
                    c += s_red[w]; p += s_red[4+w]; n += s_red[8+w];
                    co += s_red[12+w]; g += s_red[16+w];
                }
                float* gp = g_part_main + (size_t)m * 5;
                gp[0] = c; gp[1] = p; gp[2] = n; gp[3] = co; gp[4] = g;
            }
        }
        else {
            // ---------------- chamfer tile ----------------
            const int c   = tile - T_CHAM;
            const int b   = c >> 1;
            const int dir = c & 1;
            const float* srcp = (dir ? gt : recon) + (size_t)b * NV * 3;
            const float* tgtp = (dir ? recon : gt) + (size_t)b * NV * 3;
            float* tmx = S;        float* tmy = S + VP;
            float* tmz = S + 2*VP; float* tcc = S + 3*VP;
            for (int v = tid; v < VP; v += TPB) {
                if (v < NV) {
                    float x = tgtp[3*v+0], y = tgtp[3*v+1], z = tgtp[3*v+2];
                    tmx[v] = -2.f*x; tmy[v] = -2.f*y; tmz[v] = -2.f*z;
                    tcc[v] = fmaf(z, z, fmaf(y, y, x*x));
                } else { tmx[v]=0.f; tmy[v]=0.f; tmz[v]=0.f; tcc[v]=3e37f; }
            }
            __syncthreads();

            const int CROWS = 7;
            u64 CAX[CROWS], CAY[CROWS], CAZ[CROWS];
            float ca2[CROWS];
            bool  cok[CROWS];
            #pragma unroll
            for (int s = 0; s < CROWS; s++) {
                int r = tid + s * TPB;
                cok[s] = (r < NV);
                float x = 0.f, y = 0.f, z = 0.f;
                if (cok[s]) { x = srcp[3*r+0]; y = srcp[3*r+1]; z = srcp[3*r+2]; }
                ca2[s] = fmaf(z, z, fmaf(y, y, x*x));
                CAX[s] = bcast2(x); CAY[s] = bcast2(y); CAZ[s] = bcast2(z);
            }
            float cm0[CROWS], cm1[CROWS];
            #pragma unroll
            for (int s = 0; s < CROWS; s++) { cm0[s] = 3e38f; cm1[s] = 3e38f; }

            #pragma unroll 1
            for (int t = 0; t < VP; t += 4) {
                ulonglong2 X = *(const ulonglong2*)(tmx + t);
                ulonglong2 Y = *(const ulonglong2*)(tmy + t);
                ulonglong2 Z = *(const ulonglong2*)(tmz + t);
                ulonglong2 C = *(const ulonglong2*)(tcc + t);
                #pragma unroll
                for (int s = 0; s < CROWS; s++) {
                    u64 d2 = ffma2(CAZ[s], Z.x, ffma2(CAY[s], Y.x, ffma2(CAX[s], X.x, C.x)));
                    float lo, hi; unpack2f(d2, lo, hi);
                    cm0[s] = fminf(cm0[s], lo); cm1[s] = fminf(cm1[s], hi);
                    d2 = ffma2(CAZ[s], Z.y, ffma2(CAY[s], Y.y, ffma2(CAX[s], X.y, C.y)));
                    unpack2f(d2, lo, hi);
                    cm0[s] = fminf(cm0[s], lo); cm1[s] = fminf(cm1[s], hi);
                }
            }
            float part = 0.f;
            #pragma unroll
            for (int s = 0; s < CROWS; s++)
                if (cok[s]) part += fmaxf(fminf(cm0[s], cm1[s]) + ca2[s], 0.f);

            for (int off = 16; off; off >>= 1) part += __shfl_down_sync(0xFFFFFFFFu, part, off);
            if ((tid & 31) == 0) s_red[tid >> 5] = part;
            __syncthreads();
            if (tid == 0)
                g_part_cham[c] = s_red[0] + s_red[1] + s_red[2] + s_red[3];
        }
    }

    // ---------------- completion: last block does final combine ----------------
    __syncthreads();
    if (tid == 0) {
        __threadfence();
        int r = atomicAdd(&g_fin, 1);
        s_tile = (r == NBLOCKS - 1) ? 1 : 0;
    }
    __syncthreads();
    if (s_tile) {
        __threadfence();
        float sp = 0.f, sk = 0.f, sc = 0.f;
        float scm = 0.f, spe = 0.f, snp = 0.f, sco = 0.f, sgt = 0.f;
        for (int i = tid; i < BN * 61; i += TPB) { float d = rp[i] - xp[i]; sp += d * d; }
        for (int i = tid; i < BN * 64; i += TPB) {
            float m = mean[i], lv = logv[i];
            sk += 1.f + lv - m*m - expf(lv);
        }
        for (int i = tid; i < NTILE_CHAM; i += TPB) sc += g_part_cham[i];
        for (int i = tid; i < NTILE_MAIN; i += TPB) {
            const float* gp = g_part_main + (size_t)i * 5;
            scm += gp[0]; spe += gp[1]; snp += gp[2]; sco += gp[3]; sgt += gp[4];
        }
        for (int off = 16; off; off >>= 1) {
            sp  += __shfl_down_sync(0xFFFFFFFFu, sp,  off);
            sk  += __shfl_down_sync(0xFFFFFFFFu, sk,  off);
            sc  += __shfl_down_sync(0xFFFFFFFFu, sc,  off);
            scm += __shfl_down_sync(0xFFFFFFFFu, scm, off);
            spe += __shfl_down_sync(0xFFFFFFFFu, spe, off);
            snp += __shfl_down_sync(0xFFFFFFFFu, snp, off);
            sco += __shfl_down_sync(0xFFFFFFFFu, sco, off);
            sgt += __shfl_down_sync(0xFFFFFFFFu, sgt, off);
        }
        const int wid = tid >> 5;
        if ((tid & 31) == 0) {
            s_red[wid]      = sp;  s_red[4 + wid]  = sk;
            s_red[8 + wid]  = sc;  s_red[12 + wid] = scm;
            S[wid] = spe; S[4 + wid] = snp; S[8 + wid] = sco; S[12 + wid] = sgt;
        }
        __syncthreads();
        if (tid == 0) {
            float t0=0,t1=0,t2=0,t3=0,t4=0,t5=0,t6=0,t7=0;
            for (int w = 0; w < 4; w++) {
                t0 += s_red[w]; t1 += s_red[4+w]; t2 += s_red[8+w]; t3 += s_red[12+w];
                t4 += S[w];     t5 += S[4+w];     t6 += S[8+w];     t7 += S[12+w];
            }
            double param_loss  = (double)t0 / 64.0;
            double KLD         = -0.5 * (double)t1 / 64.0 * 10.0;
            double recon_loss  = (double)t2 / 64.0;
            double cmap_loss   = 3000.0 * (double)t3 / (64.0 * (double)t5);
            double consistency = -5.0 * (double)t6 / ((double)t7 + 0.0001);
            double penetr      = 100.0 * (double)t4 / 64.0;
            double loss = (recon_loss + KLD) + 0.1 * param_loss
                        + 1000.0 * cmap_loss + 10.0 * consistency + 10.0 * penetr;
            out[0] = (float)loss;
            // reset counters for deterministic graph replay
            g_ticket = 0; g_done = 0; g_mapdone = 0; g_fin = 0;
            __threadfence();
        }
    }
}

extern "C" void kernel_launch(void* const* d_in, const int* in_sizes, int n_in,
                              void* d_out, int out_size) {
    const float* obj   = (const float*)d_in[0];
    const float* recon = (const float*)d_in[1];
    const float* gt    = (const float*)d_in[2];
    const float* mean  = (const float*)d_in[3];
    const float* logv  = (const float*)d_in[4];
    const float* rp    = (const float*)d_in[5];
    const float* xp    = (const float*)d_in[6];
    const int*   faces = (const int*)d_in[7];
    float* out = (float*)d_out;

    k_mega<<<NBLOCKS, TPB>>>(obj, recon, gt, faces, mean, logv, rp, xp, out);
}